// round 9
// baseline (speedup 1.0000x reference)
#include <cuda_runtime.h>
#include <cuda_fp16.h>
#include <math.h>

#define BB 64     // batch
#define TT 64     // encoder tokens
#define EE 2048   // embed dim
#define GG 4096   // GLU hidden
#define II 256    // image token count (KV cache length)
#define HH 32     // heads
#define DD 64     // head dim

// ---------------- scratch (device globals; no runtime allocation) ----------
__device__ float g_x0  [BB * EE];
__device__ float g_q   [BB * EE];
__device__ float g_attn[BB * EE];
__device__ float g_ds1 [BB * EE];
__device__ float g_ds2 [BB * EE];
__device__ float g_x1  [BB * EE];
__device__ float g_q1  [BB * EE];
__device__ float g_z2  [BB * GG];
__device__ float g_part[12 * BB * GG];      // split-K / multi-weight partials
__device__ float g_r   [BB * HH * EE];      // r[b,h,e]
__device__ float g_ctx [BB * HH * EE];      // ctx[b,h,e]
__device__ float g_wb  [BB * HH * TT];      // softmax weights

// ---------------- fp16 / cp.async helpers -----------------------------------
__device__ __forceinline__ unsigned pack_h2(float lo, float hi) {
    __half2 h = __floats2half2_rn(lo, hi);
    return *(unsigned*)&h;
}
__device__ __forceinline__ void mma_f16(float c[4], const unsigned a[4], const unsigned b[2]) {
    asm volatile(
        "mma.sync.aligned.m16n8k16.row.col.f32.f16.f16.f32 "
        "{%0,%1,%2,%3}, {%4,%5,%6,%7}, {%8,%9}, {%0,%1,%2,%3};"
        : "+f"(c[0]), "+f"(c[1]), "+f"(c[2]), "+f"(c[3])
        : "r"(a[0]), "r"(a[1]), "r"(a[2]), "r"(a[3]), "r"(b[0]), "r"(b[1]));
}
__device__ __forceinline__ void cp_async16(void* sptr, const void* gptr) {
    unsigned sa = (unsigned)__cvta_generic_to_shared(sptr);
    asm volatile("cp.async.cg.shared.global [%0], [%1], 16;\n" :: "r"(sa), "l"(gptr));
}
__device__ __forceinline__ void cp_commit() {
    asm volatile("cp.async.commit_group;\n" ::: "memory");
}
template<int N>
__device__ __forceinline__ void cp_wait() {
    asm volatile("cp.async.wait_group %0;\n" :: "n"(N) : "memory");
}

// ---------------- pipelined GEMM for small (M=64) GEMMs (f32 staged) -------
template<int BM, int BN, int BK, int WM, int WN, int THREADS, int STAGES>
__global__ __launch_bounds__(THREADS)
void gemm_pipe(const float* __restrict__ A,
               const float* __restrict__ B0, const float* __restrict__ B1,
               const float* __restrict__ B2,
               float* __restrict__ C, int M, int N, int K, int kSplit) {
    constexpr int BKP = BK + 4;
    constexpr int BNP = BN + 8;
    extern __shared__ float smem[];
    float* As = smem;
    float* Bs = smem + STAGES * BM * BKP;

    const int z = blockIdx.z;
    const int w = z / kSplit;
    const int zz = z % kSplit;
    const float* B = (w == 0) ? B0 : ((w == 1) ? B1 : B2);
    float* Cout = C + (size_t)z * M * N;
    const int kPer = K / kSplit;
    const int kBeg = zz * kPer;

    const int n0 = blockIdx.x * BN;
    const int m0 = blockIdx.y * BM;
    const int tid = threadIdx.x;
    const int lane = tid & 31;
    const int warp = tid >> 5;
    constexpr int WARPS_N = BN / WN;
    const int wm = (warp / WARPS_N) * WM;
    const int wn = (warp % WARPS_N) * WN;
    const int gid = lane >> 2;
    const int tig = lane & 3;
    constexpr int MI = WM / 16;
    constexpr int NI = WN / 8;

    float cfr[MI][NI][4];
#pragma unroll
    for (int mi = 0; mi < MI; mi++)
#pragma unroll
        for (int ni = 0; ni < NI; ni++)
#pragma unroll
            for (int r = 0; r < 4; r++) cfr[mi][ni][r] = 0.f;

    constexpr int A4 = BM * BK / 4;
    constexpr int B4 = BK * BN / 4;
    constexpr int ALD = A4 / THREADS;
    constexpr int BLD = B4 / THREADS;
    static_assert(ALD * THREADS == A4 && BLD * THREADS == B4, "load mapping");

    auto issue = [&](int it, int buf) {
        const int kb = kBeg + it * BK;
        float* as = As + buf * BM * BKP;
        float* bs = Bs + buf * BK * BNP;
#pragma unroll
        for (int i = 0; i < ALD; i++) {
            int j = tid + i * THREADS;
            int m = j / (BK / 4), kq = j % (BK / 4);
            cp_async16(as + m * BKP + kq * 4, A + (size_t)(m0 + m) * K + kb + kq * 4);
        }
#pragma unroll
        for (int i = 0; i < BLD; i++) {
            int j = tid + i * THREADS;
            int kr = j / (BN / 4), nq = j % (BN / 4);
            cp_async16(bs + kr * BNP + nq * 4, B + (size_t)(kb + kr) * N + n0 + nq * 4);
        }
        cp_commit();
    };

    auto compute = [&](int buf) {
        const float* as = As + buf * BM * BKP;
        const float* bs = Bs + buf * BK * BNP;
#pragma unroll
        for (int kc = 0; kc < BK; kc += 16) {
            unsigned af[MI][4], bf[NI][2];
#pragma unroll
            for (int mi = 0; mi < MI; mi++) {
                int r = wm + mi * 16 + gid;
                float2 p0 = *(const float2*)(as + (size_t)(r)     * BKP + kc + 2 * tig);
                float2 p1 = *(const float2*)(as + (size_t)(r + 8) * BKP + kc + 2 * tig);
                float2 p2 = *(const float2*)(as + (size_t)(r)     * BKP + kc + 2 * tig + 8);
                float2 p3 = *(const float2*)(as + (size_t)(r + 8) * BKP + kc + 2 * tig + 8);
                af[mi][0] = pack_h2(p0.x, p0.y);
                af[mi][1] = pack_h2(p1.x, p1.y);
                af[mi][2] = pack_h2(p2.x, p2.y);
                af[mi][3] = pack_h2(p3.x, p3.y);
            }
#pragma unroll
            for (int ni = 0; ni < NI; ni++) {
                int cn = wn + ni * 8 + gid;
                bf[ni][0] = pack_h2(bs[(kc + 2 * tig)     * BNP + cn],
                                    bs[(kc + 2 * tig + 1) * BNP + cn]);
                bf[ni][1] = pack_h2(bs[(kc + 2 * tig + 8) * BNP + cn],
                                    bs[(kc + 2 * tig + 9) * BNP + cn]);
            }
#pragma unroll
            for (int mi = 0; mi < MI; mi++)
#pragma unroll
                for (int ni = 0; ni < NI; ni++)
                    mma_f16(cfr[mi][ni], af[mi], bf[ni]);
        }
    };

    const int nIter = kPer / BK;
#pragma unroll
    for (int s = 0; s < STAGES - 1; s++) issue(s, s);
    for (int it = 0; it < nIter; ++it) {
        cp_wait<STAGES - 2>();
        __syncthreads();
        const int nx = it + STAGES - 1;
        if (nx < nIter) issue(nx, nx % STAGES); else cp_commit();
        compute(it % STAGES);
    }

#pragma unroll
    for (int mi = 0; mi < MI; mi++) {
#pragma unroll
        for (int ni = 0; ni < NI; ni++) {
            int row = m0 + wm + mi * 16 + gid;
            int col = n0 + wn + ni * 8 + tig * 2;
            *(float2*)(&Cout[(size_t)row * N + col]) =
                make_float2(cfr[mi][ni][0], cfr[mi][ni][1]);
            *(float2*)(&Cout[(size_t)(row + 8) * N + col]) =
                make_float2(cfr[mi][ni][2], cfr[mi][ni][3]);
        }
    }
}

// ============ restructured cross-attention (Q=1 per b,h) ====================
// step 1: r[b,h,e] = sum_c (q1[b,hD+c] * 0.125) * Wk[e, hD+c]
// grid (etile=8, h=32), 256 threads
__global__ void r_kernel(const float* __restrict__ q1, const float* __restrict__ Wk,
                         float* __restrict__ r) {
    __shared__ float qs[64 * 65];
    __shared__ float wk_s[64 * 65];
    const int h = blockIdx.y;
    const int e0 = blockIdx.x * 256;
    const int tid = threadIdx.x;
    // load Q_h scaled: qs[b][c]
    for (int j = tid; j < 64 * 64; j += 256) {
        int b = j >> 6, c = j & 63;
        qs[b * 65 + c] = q1[(size_t)b * EE + h * DD + c] * 0.125f;
    }
    const int e_l = tid & 63;
    const int bg = tid >> 6;   // 0..3 -> 16 b's each
    for (int ec = 0; ec < 4; ec++) {
        __syncthreads();
        // load Wk slab [64 e][64 c]
        for (int j = tid; j < 64 * 64; j += 256) {
            int e = j >> 6, c = j & 63;
            wk_s[e * 65 + c] = Wk[(size_t)(e0 + ec * 64 + e) * EE + h * DD + c];
        }
        __syncthreads();
        float acc[16];
#pragma unroll
        for (int i = 0; i < 16; i++) acc[i] = 0.f;
#pragma unroll 8
        for (int c = 0; c < 64; c++) {
            float wk = wk_s[e_l * 65 + c];
#pragma unroll
            for (int i = 0; i < 16; i++)
                acc[i] += qs[(bg * 16 + i) * 65 + c] * wk;
        }
        const int e = e0 + ec * 64 + e_l;
#pragma unroll
        for (int i = 0; i < 16; i++) {
            int b = bg * 16 + i;
            r[((size_t)b * HH + h) * EE + e] = acc[i];
        }
    }
}

// step 2a: scores[b,h,t] = enc[b,t,:]·r[b,h,:] + maskbias; softmax -> wb
// grid (hg=4, b=64), 256 threads; each block: 8 heads
__global__ void scores_kernel(const float* __restrict__ enc, const float* __restrict__ r,
                              const int* __restrict__ mask, float* __restrict__ wb) {
    __shared__ float enc_s[64 * 129];
    __shared__ float r_s[8 * 128];
    __shared__ float sc[8][64];
    const int b = blockIdx.y;
    const int hg = blockIdx.x;
    const int tid = threadIdx.x;
    const int h0 = tid >> 6;      // 0..3 (also handles h0+4)
    const int t  = tid & 63;
    float acc0 = 0.f, acc1 = 0.f;
    for (int e0 = 0; e0 < EE; e0 += 128) {
        __syncthreads();
        for (int j = tid; j < 64 * 128; j += 256) {
            int tt = j >> 7, e = j & 127;
            enc_s[tt * 129 + e] = enc[((size_t)b * TT + tt) * EE + e0 + e];
        }
        for (int j = tid; j < 8 * 128; j += 256) {
            int hl = j >> 7, e = j & 127;
            r_s[hl * 128 + e] = r[((size_t)b * HH + hg * 8 + hl) * EE + e0 + e];
        }
        __syncthreads();
#pragma unroll 4
        for (int e = 0; e < 128; e++) {
            float ev = enc_s[t * 129 + e];
            acc0 += ev * r_s[h0 * 128 + e];
            acc1 += ev * r_s[(h0 + 4) * 128 + e];
        }
    }
    const float bias = (1.0f - (float)mask[b * TT + t]) * -1e12f;
    sc[h0][t]     = acc0 + bias;
    sc[h0 + 4][t] = acc1 + bias;
    __syncthreads();
    // softmax: warp w handles head (hg*8 + w)
    const int w = tid >> 5, l = tid & 31;
    float s0 = sc[w][l], s1 = sc[w][l + 32];
    float m = fmaxf(s0, s1);
#pragma unroll
    for (int o = 16; o; o >>= 1) m = fmaxf(m, __shfl_xor_sync(0xffffffffu, m, o));
    float e0v = __expf(s0 - m), e1v = __expf(s1 - m);
    float sum = e0v + e1v;
#pragma unroll
    for (int o = 16; o; o >>= 1) sum += __shfl_xor_sync(0xffffffffu, sum, o);
    const float inv = 1.0f / sum;
    wb[((size_t)b * HH + hg * 8 + w) * TT + l]      = e0v * inv;
    wb[((size_t)b * HH + hg * 8 + w) * TT + l + 32] = e1v * inv;
}

// step 2b: ctx[b,h,e] = sum_t wb[b,h,t] * enc[b,t,e]
// grid (e8=8, b=64), 256 threads; each thread one e, all 32 h
__global__ void ctx_kernel(const float* __restrict__ enc, const float* __restrict__ wb,
                           float* __restrict__ ctx) {
    __shared__ float ws[HH * TT];
    const int b = blockIdx.y;
    const int e = blockIdx.x * 256 + threadIdx.x;
    for (int j = threadIdx.x; j < HH * TT; j += 256)
        ws[j] = wb[(size_t)b * HH * TT + j];
    __syncthreads();
    float acc[HH];
#pragma unroll
    for (int h = 0; h < HH; h++) acc[h] = 0.f;
    for (int t = 0; t < TT; t++) {
        float ev = enc[((size_t)b * TT + t) * EE + e];
#pragma unroll
        for (int h = 0; h < HH; h++)
            acc[h] += ws[h * TT + t] * ev;
    }
#pragma unroll
    for (int h = 0; h < HH; h++)
        ctx[((size_t)b * HH + h) * EE + e] = acc[h];
}

// step 3: out_part[z][b, hD+c] = sum_{e in z-range} ctx[b,h,e] * Wv[e, hD+c]
// grid (z=8, h=32), 256 threads; reduce afterwards
__global__ void outp_kernel(const float* __restrict__ ctx, const float* __restrict__ Wv,
                            float* __restrict__ part) {
    __shared__ float ctx_s[64 * 65];
    __shared__ float wv_s[64 * 65];
    const int h = blockIdx.y;
    const int z = blockIdx.x;
    const int e0 = z * 256;
    const int tid = threadIdx.x;
    const int c  = tid & 63;
    const int bg = tid >> 6;   // 0..3 -> 16 b's
    float acc[16];
#pragma unroll
    for (int i = 0; i < 16; i++) acc[i] = 0.f;
    for (int ec = 0; ec < 4; ec++) {
        __syncthreads();
        for (int j = tid; j < 64 * 64; j += 256) {
            int bb = j >> 6, e = j & 63;
            ctx_s[bb * 65 + e] = ctx[((size_t)bb * HH + h) * EE + e0 + ec * 64 + e];
        }
        for (int j = tid; j < 64 * 64; j += 256) {
            int e = j >> 6, cc = j & 63;
            wv_s[e * 65 + cc] = Wv[(size_t)(e0 + ec * 64 + e) * EE + h * DD + cc];
        }
        __syncthreads();
#pragma unroll 8
        for (int e = 0; e < 64; e++) {
            float wv = wv_s[e * 65 + c];
#pragma unroll
            for (int i = 0; i < 16; i++)
                acc[i] += ctx_s[(bg * 16 + i) * 65 + e] * wv;
        }
    }
#pragma unroll
    for (int i = 0; i < 16; i++) {
        int b = bg * 16 + i;
        part[(size_t)z * BB * EE + (size_t)b * EE + h * DD + c] = acc[i];
    }
}

// ---------------- reductions / fused epilogues -------------------------------
__global__ void reduce_ws(const float* __restrict__ part, float* __restrict__ out,
                          int mn, int W, int S) {
    int i = (blockIdx.x * blockDim.x + threadIdx.x) * 4;
    if (i >= W * mn) return;
    int w = i / mn, e = i % mn;
    const float* p = part + (size_t)(w * S) * mn + e;
    float4 acc = *(const float4*)p;
    for (int zx = 1; zx < S; zx++) {
        float4 t = *(const float4*)(p + (size_t)zx * mn);
        acc.x += t.x; acc.y += t.y; acc.z += t.z; acc.w += t.w;
    }
    *(float4*)(out + i) = acc;
}

__global__ void reduce_qkv_scatter(const float* __restrict__ part,
                                   float* __restrict__ qbuf,
                                   float* __restrict__ cache,
                                   const int* __restrict__ tokp, int S) {
    int i = (blockIdx.x * blockDim.x + threadIdx.x) * 4;
    if (i >= 3 * BB * EE) return;
    const int w = i / (BB * EE);
    const int e = i % (BB * EE);
    const float* p = part + (size_t)(w * S) * (BB * EE) + e;
    float4 acc = *(const float4*)p;
    for (int zx = 1; zx < S; zx++) {
        float4 t = *(const float4*)(p + (size_t)zx * (BB * EE));
        acc.x += t.x; acc.y += t.y; acc.z += t.z; acc.w += t.w;
    }
    const int tok = *tokp;
    const int b = e / EE, c = e % EE;
    if (w == 0)      *(float4*)(&cache[((size_t)b * II + tok) * EE + c]) = acc;
    else if (w == 1) *(float4*)(&cache[((size_t)(BB + b) * II + tok) * EE + c]) = acc;
    else             *(float4*)(&qbuf[e]) = acc;
}

__device__ __forceinline__ float gelu_exact(float x) {
    return 0.5f * x * (1.0f + erff(x * 0.70710678118654752f));
}

__global__ void ln_reduce_kernel(const float* __restrict__ part, int S,
                                 const float* __restrict__ scale,
                                 const float* __restrict__ bias,
                                 const float* __restrict__ residual,
                                 float* __restrict__ out) {
    __shared__ float buf[EE];
    __shared__ float rs[8], rs2[8];
    const int row = blockIdx.x;
    const int t = threadIdx.x;
    float s = 0.f, s2 = 0.f;
    for (int c = t * 4; c < EE; c += 256 * 4) {
        const float* p = part + (size_t)row * EE + c;
        float4 acc = *(const float4*)p;
        for (int zx = 1; zx < S; zx++) {
            float4 v = *(const float4*)(p + (size_t)zx * BB * EE);
            acc.x += v.x; acc.y += v.y; acc.z += v.z; acc.w += v.w;
        }
        *(float4*)(&buf[c]) = acc;
        s  += acc.x + acc.y + acc.z + acc.w;
        s2 += acc.x*acc.x + acc.y*acc.y + acc.z*acc.z + acc.w*acc.w;
    }
#pragma unroll
    for (int o = 16; o; o >>= 1) {
        s  += __shfl_down_sync(0xffffffffu, s, o);
        s2 += __shfl_down_sync(0xffffffffu, s2, o);
    }
    const int w = t >> 5;
    if ((t & 31) == 0) { rs[w] = s; rs2[w] = s2; }
    __syncthreads();
    if (t == 0) {
        float a = 0.f, b = 0.f;
        for (int i = 0; i < 8; i++) { a += rs[i]; b += rs2[i]; }
        rs[0] = a; rs2[0] = b;
    }
    __syncthreads();
    const float mu  = rs[0] / (float)EE;
    const float var = rs2[0] / (float)EE - mu * mu;
    const float inv = rsqrtf(var + 1e-6f);
    for (int c = t; c < EE; c += 256) {
        out[(size_t)row * EE + c] = (buf[c] - mu) * inv * scale[c] + bias[c]
                                    + residual[(size_t)row * EE + c];
    }
}

__global__ void ln_glu_kernel(const float* __restrict__ part, int S,
                              const float* __restrict__ scale,
                              const float* __restrict__ bias,
                              float* __restrict__ out) {
    __shared__ float buf[GG];
    __shared__ float rs[8], rs2[8];
    const int row = blockIdx.x;
    const int t = threadIdx.x;
    float s = 0.f, s2 = 0.f;
    for (int c = t * 4; c < GG; c += 256 * 4) {
        const float* pa = part + (size_t)row * GG + c;
        const float* pb = pa + (size_t)S * BB * GG;
        float4 a = *(const float4*)pa;
        float4 b = *(const float4*)pb;
        for (int zx = 1; zx < S; zx++) {
            float4 ta = *(const float4*)(pa + (size_t)zx * BB * GG);
            float4 tb = *(const float4*)(pb + (size_t)zx * BB * GG);
            a.x += ta.x; a.y += ta.y; a.z += ta.z; a.w += ta.w;
            b.x += tb.x; b.y += tb.y; b.z += tb.z; b.w += tb.w;
        }
        float4 r;
        r.x = gelu_exact(a.x) * b.x;
        r.y = gelu_exact(a.y) * b.y;
        r.z = gelu_exact(a.z) * b.z;
        r.w = gelu_exact(a.w) * b.w;
        *(float4*)(&buf[c]) = r;
        s  += r.x + r.y + r.z + r.w;
        s2 += r.x*r.x + r.y*r.y + r.z*r.z + r.w*r.w;
    }
#pragma unroll
    for (int o = 16; o; o >>= 1) {
        s  += __shfl_down_sync(0xffffffffu, s, o);
        s2 += __shfl_down_sync(0xffffffffu, s2, o);
    }
    const int w = t >> 5;
    if ((t & 31) == 0) { rs[w] = s; rs2[w] = s2; }
    __syncthreads();
    if (t == 0) {
        float a = 0.f, b = 0.f;
        for (int i = 0; i < 8; i++) { a += rs[i]; b += rs2[i]; }
        rs[0] = a; rs2[0] = b;
    }
    __syncthreads();
    const float mu  = rs[0] / (float)GG;
    const float var = rs2[0] / (float)GG - mu * mu;
    const float inv = rsqrtf(var + 1e-6f);
    for (int c = t; c < GG; c += 256) {
        out[(size_t)row * GG + c] = (buf[c] - mu) * inv * scale[c] + bias[c];
    }
}

__global__ void reduce_add(const float* __restrict__ part, const float* __restrict__ res,
                           float* __restrict__ out, int mn, int S) {
    int i = (blockIdx.x * blockDim.x + threadIdx.x) * 4;
    if (i >= mn) return;
    float4 acc = *(const float4*)(part + i);
    for (int zx = 1; zx < S; zx++) {
        float4 t = *(const float4*)(part + (size_t)zx * mn + i);
        acc.x += t.x; acc.y += t.y; acc.z += t.z; acc.w += t.w;
    }
    float4 r = *(const float4*)(res + i);
    acc.x += r.x; acc.y += r.y; acc.z += r.z; acc.w += r.w;
    *(float4*)(out + i) = acc;
}

// ---------------- LayerNorm ---------------------------------------------------
__global__ void ln_kernel(const float* __restrict__ in,
                          const float* __restrict__ scale,
                          const float* __restrict__ bias,
                          const float* __restrict__ residual,
                          float* __restrict__ out, int cols) {
    const int row = blockIdx.x;
    const float* x = in + (size_t)row * cols;
    float s = 0.f, s2 = 0.f;
    for (int c = threadIdx.x; c < cols; c += 256) {
        float v = x[c]; s += v; s2 += v * v;
    }
#pragma unroll
    for (int o = 16; o; o >>= 1) {
        s  += __shfl_down_sync(0xffffffffu, s, o);
        s2 += __shfl_down_sync(0xffffffffu, s2, o);
    }
    __shared__ float rs[8], rs2[8];
    const int w = threadIdx.x >> 5;
    if ((threadIdx.x & 31) == 0) { rs[w] = s; rs2[w] = s2; }
    __syncthreads();
    if (threadIdx.x == 0) {
        float a = 0.f, b = 0.f;
        for (int i = 0; i < 8; i++) { a += rs[i]; b += rs2[i]; }
        rs[0] = a; rs2[0] = b;
    }
    __syncthreads();
    const float mu  = rs[0] / (float)cols;
    const float var = rs2[0] / (float)cols - mu * mu;
    const float inv = rsqrtf(var + 1e-6f);
    for (int c = threadIdx.x; c < cols; c += 256) {
        float y = (x[c] - mu) * inv;
        if (scale)    y *= scale[c];
        if (bias)     y += bias[c];
        if (residual) y += residual[(size_t)row * cols + c];
        out[(size_t)row * cols + c] = y;
    }
}

// ---------------- self-attention (Q=1), 256-thread cooperative -------------
__global__ void self_attn_kernel(const float* __restrict__ q,
                                 const float* __restrict__ cache,
                                 const int* __restrict__ tokp,
                                 float* __restrict__ out) {
    const int bh = blockIdx.x;
    const int b = bh >> 5, h = bh & 31;
    int nk = *tokp + 1;
    if (nk > II) nk = II;
    __shared__ float sq[DD];
    __shared__ float sl[II];
    __shared__ float red[4 * DD];
    __shared__ float sume[4];
    __shared__ float smax;
    const int t = threadIdx.x;
    if (t < DD) sq[t] = q[(size_t)b * EE + h * DD + t] * 0.125f;
    __syncthreads();
    if (t < nk) {
        const float4* kp = (const float4*)(cache + ((size_t)b * II + t) * EE + h * DD);
        float s = 0.f;
#pragma unroll
        for (int c = 0; c < DD / 4; c++) {
            float4 v = kp[c];
            s += sq[4*c] * v.x + sq[4*c+1] * v.y + sq[4*c+2] * v.z + sq[4*c+3] * v.w;
        }
        sl[t] = s;
    }
    __syncthreads();
    if (t < 32) {
        float m = -1e30f;
        for (int k = t; k < nk; k += 32) m = fmaxf(m, sl[k]);
#pragma unroll
        for (int o = 16; o; o >>= 1) m = fmaxf(m, __shfl_down_sync(0xffffffffu, m, o));
        if (t == 0) smax = m;
    }
    __syncthreads();
    const float m = smax;
    const int g = t >> 6, d = t & 63;
    const int kpg = (nk + 3) >> 2;
    const int k0 = g * kpg;
    int k1 = k0 + kpg; if (k1 > nk) k1 = nk;
    const float* vb = cache + (size_t)(BB + b) * II * EE + h * DD + d;
    float se = 0.f, acc = 0.f;
    for (int k = k0; k < k1; k++) {
        float e = __expf(sl[k] - m);
        se += e;
        acc += e * vb[(size_t)k * EE];
    }
    red[t] = acc;
    if (d == 0) sume[g] = se;
    __syncthreads();
    if (t < DD) {
        float a = red[t] + red[DD + t] + red[2 * DD + t] + red[3 * DD + t];
        float s = sume[0] + sume[1] + sume[2] + sume[3];
        out[(size_t)b * EE + h * DD + t] = a / s;
    }
}

// ---------------------------------------------------------------------------
#define GEMM_SMALL_T gemm_pipe<64,64,32,32,16,256,4>
#define SMEM_SMALL   ((4*(64*36) + 4*(32*72)) * 4)

extern "C" void kernel_launch(void* const* d_in, const int* in_sizes, int n_in,
                              void* d_out, int out_size) {
    (void)in_sizes; (void)n_in; (void)out_size;
    const float* ds_in        = (const float*)d_in[0];
    const float* enc          = (const float*)d_in[1];
    const float* attn_in      = (const float*)d_in[2];
    const int*   attn_mask    = (const int*)  d_in[3];
    const int*   token_index  = (const int*)  d_in[4];
    const float* ln_pre_sa_b  = (const float*)d_in[5];
    const float* q_sa         = (const float*)d_in[6];
    const float* k_sa         = (const float*)d_in[7];
    const float* v_sa         = (const float*)d_in[8];
    const float* o_sa         = (const float*)d_in[9];
    const float* ln_sa_s      = (const float*)d_in[10];
    const float* ln_sa_b      = (const float*)d_in[11];
    const float* ln_pre_ca_b  = (const float*)d_in[12];
    const float* q_ca         = (const float*)d_in[13];
    const float* k_ca         = (const float*)d_in[14];
    const float* v_ca         = (const float*)d_in[15];
    const float* o_ca         = (const float*)d_in[16];
    const float* ln_ca_s      = (const float*)d_in[17];
    const float* ln_ca_b      = (const float*)d_in[18];
    const float* glu_ln0_b    = (const float*)d_in[19];
    const float* fc0_w        = (const float*)d_in[20];
    const float* fc1_w        = (const float*)d_in[21];
    const float* glu_ln1_s    = (const float*)d_in[22];
    const float* glu_ln1_b    = (const float*)d_in[23];
    const float* fc2_w        = (const float*)d_in[24];

    float* out_dec  = (float*)d_out;
    float* out_attn = out_dec + (size_t)BB * EE;

    float *x0, *q, *attn, *ds1, *ds2, *x1, *q1, *z2, *part, *rbuf, *ctx, *wb;
    cudaGetSymbolAddress((void**)&x0,   g_x0);
    cudaGetSymbolAddress((void**)&q,    g_q);
    cudaGetSymbolAddress((void**)&attn, g_attn);
    cudaGetSymbolAddress((void**)&ds1,  g_ds1);
    cudaGetSymbolAddress((void**)&ds2,  g_ds2);
    cudaGetSymbolAddress((void**)&x1,   g_x1);
    cudaGetSymbolAddress((void**)&q1,   g_q1);
    cudaGetSymbolAddress((void**)&z2,   g_z2);
    cudaGetSymbolAddress((void**)&part, g_part);
    cudaGetSymbolAddress((void**)&rbuf, g_r);
    cudaGetSymbolAddress((void**)&ctx,  g_ctx);
    cudaGetSymbolAddress((void**)&wb,   g_wb);

    cudaFuncSetAttribute(GEMM_SMALL_T, cudaFuncAttributeMaxDynamicSharedMemorySize, SMEM_SMALL);

    // ---- persistent handles (created once; see round-7 note) ---------------
    static cudaStream_t sA = nullptr;
    static cudaEvent_t eFork = nullptr, eCopy = nullptr;
    if (sA == nullptr) {
        cudaStreamCreateWithFlags(&sA, cudaStreamNonBlocking);
        cudaEventCreateWithFlags(&eFork, cudaEventDisableTiming);
        cudaEventCreateWithFlags(&eCopy, cudaEventDisableTiming);
    }

    cudaEventRecord(eFork, 0);
    cudaStreamWaitEvent(sA, eFork, 0);

    // branch A: KV-cache pass-through copy (CE), overlapped with self block
    cudaMemcpyAsync(out_attn, attn_in, (size_t)2 * BB * II * EE * sizeof(float),
                    cudaMemcpyDeviceToDevice, sA);
    cudaEventRecord(eCopy, sA);

    // ---- self-attention block -----------------------------------------------
    ln_kernel<<<BB, 256>>>(ds_in, nullptr, ln_pre_sa_b, nullptr, x0, EE);
    GEMM_SMALL_T<<<dim3(EE/64, 1, 3*8), 256, SMEM_SMALL>>>(x0, k_sa, v_sa, q_sa,
                                                           part, BB, EE, EE, 8);
    cudaStreamWaitEvent(0, eCopy, 0);
    reduce_qkv_scatter<<<(3*BB*EE/4 + 255)/256, 256>>>(part, q, out_attn, token_index, 8);
    self_attn_kernel<<<BB*HH, 256>>>(q, out_attn, token_index, attn);
    GEMM_SMALL_T<<<dim3(EE/64, 1, 8), 256, SMEM_SMALL>>>(attn, o_sa, o_sa, o_sa,
                                                         part, BB, EE, EE, 8);
    ln_reduce_kernel<<<BB, 256>>>(part, 8, ln_sa_s, ln_sa_b, ds_in, ds1);

    // ---- cross-attention block (restructured, no big GEMM) ------------------
    ln_kernel<<<BB, 256>>>(ds1, nullptr, ln_pre_ca_b, nullptr, x1, EE);
    GEMM_SMALL_T<<<dim3(EE/64, 1, 8), 256, SMEM_SMALL>>>(x1, q_ca, q_ca, q_ca,
                                                         part, BB, EE, EE, 8);
    reduce_ws<<<(BB*EE/4 + 255)/256, 256>>>(part, q1, BB*EE, 1, 8);
    r_kernel     <<<dim3(8, HH), 256>>>(q1, k_ca, rbuf);
    scores_kernel<<<dim3(4, BB), 256>>>(enc, rbuf, attn_mask, wb);
    ctx_kernel   <<<dim3(8, BB), 256>>>(enc, wb, ctx);
    outp_kernel  <<<dim3(8, HH), 256>>>(ctx, v_ca, part);
    reduce_ws<<<(BB*EE/4 + 255)/256, 256>>>(part, attn, BB*EE, 1, 8);
    GEMM_SMALL_T<<<dim3(EE/64, 1, 8), 256, SMEM_SMALL>>>(attn, o_ca, o_ca, o_ca,
                                                         part, BB, EE, EE, 8);
    ln_reduce_kernel<<<BB, 256>>>(part, 8, ln_ca_s, ln_ca_b, ds1, ds2);

    // ---- GLU feed-forward block ---------------------------------------------
    ln_kernel<<<BB, 256>>>(ds2, nullptr, glu_ln0_b, nullptr, x0, EE);
    GEMM_SMALL_T<<<dim3(GG/64, 1, 2*4), 256, SMEM_SMALL>>>(x0, fc0_w, fc1_w, fc1_w,
                                                           part, BB, GG, EE, 4);
    ln_glu_kernel<<<BB, 256>>>(part, 4, glu_ln1_s, glu_ln1_b, z2);
    GEMM_SMALL_T<<<dim3(EE/64, 1, 8), 256, SMEM_SMALL>>>(z2, fc2_w, fc2_w, fc2_w,
                                                         part, BB, EE, GG, 8);
    reduce_add<<<(BB*EE/4 + 255)/256, 256>>>(part, ds2, out_dec, BB*EE, 8);
}

// round 10
// speedup vs baseline: 1.5981x; 1.5981x over previous
#include <cuda_runtime.h>
#include <cuda_fp16.h>
#include <math.h>

#define BB 64     // batch
#define TT 64     // encoder tokens
#define EE 2048   // embed dim
#define GG 4096   // GLU hidden
#define II 256    // image token count (KV cache length)
#define HH 32     // heads
#define DD 64     // head dim

// ---------------- scratch (device globals; no runtime allocation) ----------
__device__ float g_x0  [BB * EE];
__device__ float g_q   [BB * EE];
__device__ float g_attn[BB * EE];
__device__ float g_ds1 [BB * EE];
__device__ float g_ds2 [BB * EE];
__device__ float g_x1  [BB * EE];
__device__ float g_q1  [BB * EE];
__device__ float g_ekv [2 * BB * TT * EE];  // ek then ev
__device__ float g_z2  [BB * GG];
__device__ float g_part[12 * BB * GG];      // split-K / multi-weight partials
__device__ __align__(16) __half g_enc_h[BB * TT * EE];
__device__ __align__(16) __half g_wk_h [EE * EE];
__device__ __align__(16) __half g_wv_h [EE * EE];

// ---------------- fp16 / cp.async / ldmatrix helpers ------------------------
__device__ __forceinline__ unsigned pack_h2(float lo, float hi) {
    __half2 h = __floats2half2_rn(lo, hi);
    return *(unsigned*)&h;
}
__device__ __forceinline__ void mma_f16(float c[4], const unsigned a[4], const unsigned b[2]) {
    asm volatile(
        "mma.sync.aligned.m16n8k16.row.col.f32.f16.f16.f32 "
        "{%0,%1,%2,%3}, {%4,%5,%6,%7}, {%8,%9}, {%0,%1,%2,%3};"
        : "+f"(c[0]), "+f"(c[1]), "+f"(c[2]), "+f"(c[3])
        : "r"(a[0]), "r"(a[1]), "r"(a[2]), "r"(a[3]), "r"(b[0]), "r"(b[1]));
}
__device__ __forceinline__ void cp_async16(void* sptr, const void* gptr) {
    unsigned sa = (unsigned)__cvta_generic_to_shared(sptr);
    asm volatile("cp.async.cg.shared.global [%0], [%1], 16;\n" :: "r"(sa), "l"(gptr));
}
__device__ __forceinline__ void cp_commit() {
    asm volatile("cp.async.commit_group;\n" ::: "memory");
}
template<int N>
__device__ __forceinline__ void cp_wait() {
    asm volatile("cp.async.wait_group %0;\n" :: "n"(N) : "memory");
}
__device__ __forceinline__ void ldsm_x4(unsigned r[4], unsigned saddr) {
    asm volatile("ldmatrix.sync.aligned.m8n8.x4.shared.b16 {%0,%1,%2,%3}, [%4];"
                 : "=r"(r[0]), "=r"(r[1]), "=r"(r[2]), "=r"(r[3]) : "r"(saddr));
}
__device__ __forceinline__ void ldsm_x4t(unsigned r[4], unsigned saddr) {
    asm volatile("ldmatrix.sync.aligned.m8n8.x4.trans.shared.b16 {%0,%1,%2,%3}, [%4];"
                 : "=r"(r[0]), "=r"(r[1]), "=r"(r[2]), "=r"(r[3]) : "r"(saddr));
}

// ---------------- f32 -> f16 conversion (3 regions, one launch) ------------
__global__ void f2h3_kernel(const float* __restrict__ a, __half* __restrict__ ah, int na,
                            const float* __restrict__ b, __half* __restrict__ bh, int nb,
                            const float* __restrict__ c, __half* __restrict__ ch, int nc) {
    int i = (blockIdx.x * blockDim.x + threadIdx.x) * 8;
    if (i >= na + nb + nc) return;
    const float* src; __half* dst; int off;
    if (i < na)           { src = a; dst = ah; off = i; }
    else if (i < na + nb) { src = b; dst = bh; off = i - na; }
    else                  { src = c; dst = ch; off = i - na - nb; }
    float4 v0 = *(const float4*)(src + off);
    float4 v1 = *(const float4*)(src + off + 4);
    __half2 h0 = __floats2half2_rn(v0.x, v0.y);
    __half2 h1 = __floats2half2_rn(v0.z, v0.w);
    __half2 h2 = __floats2half2_rn(v1.x, v1.y);
    __half2 h3 = __floats2half2_rn(v1.z, v1.w);
    uint4 o = make_uint4(*(unsigned*)&h0, *(unsigned*)&h1, *(unsigned*)&h2, *(unsigned*)&h3);
    *(uint4*)(dst + off) = o;
}

// ---------------- fp16-native big GEMM: 256x128 tiles, 512 threads ----------
// C[M,N] = A[M,K] @ Bz[K,N]; Bz = blockIdx.z ? B1 : B0; out to C + z*M*N.
__global__ __launch_bounds__(512)
void gemm_h16(const __half* __restrict__ A, const __half* __restrict__ B0,
              const __half* __restrict__ B1, float* __restrict__ C,
              int M, int N, int K) {
    constexpr int BM = 256, BN = 128, BK = 32, STAGES = 3, THREADS = 512;
    constexpr int BKP = BK + 8;    // 40 halves
    constexpr int BNP = BN + 8;    // 136 halves
    extern __shared__ char sm_[];
    __half* As = (__half*)sm_;                       // STAGES*BM*BKP
    __half* Bs = As + STAGES * BM * BKP;             // STAGES*BK*BNP

    const __half* B = blockIdx.z ? B1 : B0;
    float* Cout = C + (size_t)blockIdx.z * M * N;
    const int n0 = blockIdx.x * BN;
    const int m0 = blockIdx.y * BM;
    const int tid = threadIdx.x;
    const int lane = tid & 31;
    const int warp = tid >> 5;        // 16 warps
    const int wm = (warp >> 2) * 64;  // 4 warp-rows -> 256 m
    const int wn = (warp & 3) * 32;   // 4 warp-cols -> 128 n
    const int gid = lane >> 2, tig = lane & 3;

    float cfr[4][4][4];
#pragma unroll
    for (int mi = 0; mi < 4; mi++)
#pragma unroll
        for (int ni = 0; ni < 4; ni++)
#pragma unroll
            for (int r = 0; r < 4; r++) cfr[mi][ni][r] = 0.f;

    auto issue = [&](int it, int buf) {
        const int kb = it * BK;
        __half* as = As + buf * BM * BKP;
        __half* bs = Bs + buf * BK * BNP;
#pragma unroll
        for (int i = 0; i < 2; i++) {            // A: 1024 16B chunks / 512 thr
            int j = tid + i * THREADS;
            int row = j >> 2, kq = (j & 3) * 8;
            cp_async16(as + row * BKP + kq, A + (size_t)(m0 + row) * K + kb + kq);
        }
        {                                        // B: 512 16B chunks
            int kr = tid >> 4, nq = (tid & 15) * 8;
            cp_async16(bs + kr * BNP + nq, B + (size_t)(kb + kr) * N + n0 + nq);
        }
        cp_commit();
    };

    unsigned asb = (unsigned)__cvta_generic_to_shared(As);
    unsigned bsb = (unsigned)__cvta_generic_to_shared(Bs);
    const int l8 = lane & 7, lb = (lane >> 3) & 1, lc = lane >> 4;
    const unsigned aoff = ((wm + lb * 8 + l8) * BKP + lc * 8) * 2;
    const unsigned boff = ((lb * 8 + l8) * BNP + wn + lc * 8) * 2;

    auto compute = [&](int buf) {
        unsigned ab = asb + buf * BM * BKP * 2 + aoff;
        unsigned bb = bsb + buf * BK * BNP * 2 + boff;
#pragma unroll
        for (int kc = 0; kc < BK; kc += 16) {
            unsigned af[4][4], bf[4][2];
#pragma unroll
            for (int mi = 0; mi < 4; mi++)
                ldsm_x4(af[mi], ab + (mi * 16 * BKP + kc) * 2);
#pragma unroll
            for (int p = 0; p < 2; p++) {
                unsigned r[4];
                ldsm_x4t(r, bb + (kc * BNP + p * 16) * 2);
                bf[2 * p][0] = r[0]; bf[2 * p][1] = r[1];
                bf[2 * p + 1][0] = r[2]; bf[2 * p + 1][1] = r[3];
            }
#pragma unroll
            for (int mi = 0; mi < 4; mi++)
#pragma unroll
                for (int ni = 0; ni < 4; ni++)
                    mma_f16(cfr[mi][ni], af[mi], bf[ni]);
        }
    };

    const int nIter = K / BK;
#pragma unroll
    for (int s = 0; s < STAGES - 1; s++) issue(s, s);
    for (int it = 0; it < nIter; ++it) {
        cp_wait<STAGES - 2>();
        __syncthreads();
        const int nx = it + STAGES - 1;
        if (nx < nIter) issue(nx, nx % STAGES); else cp_commit();
        compute(it % STAGES);
    }

#pragma unroll
    for (int mi = 0; mi < 4; mi++) {
#pragma unroll
        for (int ni = 0; ni < 4; ni++) {
            int row = m0 + wm + mi * 16 + gid;
            int col = n0 + wn + ni * 8 + tig * 2;
            *(float2*)(&Cout[(size_t)row * N + col]) =
                make_float2(cfr[mi][ni][0], cfr[mi][ni][1]);
            *(float2*)(&Cout[(size_t)(row + 8) * N + col]) =
                make_float2(cfr[mi][ni][2], cfr[mi][ni][3]);
        }
    }
}

// ---------------- pipelined GEMM for small (M=64) GEMMs (f32 staged) -------
template<int BM, int BN, int BK, int WM, int WN, int THREADS, int STAGES>
__global__ __launch_bounds__(THREADS)
void gemm_pipe(const float* __restrict__ A,
               const float* __restrict__ B0, const float* __restrict__ B1,
               const float* __restrict__ B2,
               float* __restrict__ C, int M, int N, int K, int kSplit) {
    constexpr int BKP = BK + 4;
    constexpr int BNP = BN + 8;
    extern __shared__ float smem[];
    float* As = smem;
    float* Bs = smem + STAGES * BM * BKP;

    const int z = blockIdx.z;
    const int w = z / kSplit;
    const int zz = z % kSplit;
    const float* B = (w == 0) ? B0 : ((w == 1) ? B1 : B2);
    float* Cout = C + (size_t)z * M * N;
    const int kPer = K / kSplit;
    const int kBeg = zz * kPer;

    const int n0 = blockIdx.x * BN;
    const int m0 = blockIdx.y * BM;
    const int tid = threadIdx.x;
    const int lane = tid & 31;
    const int warp = tid >> 5;
    constexpr int WARPS_N = BN / WN;
    const int wm = (warp / WARPS_N) * WM;
    const int wn = (warp % WARPS_N) * WN;
    const int gid = lane >> 2;
    const int tig = lane & 3;
    constexpr int MI = WM / 16;
    constexpr int NI = WN / 8;

    float cfr[MI][NI][4];
#pragma unroll
    for (int mi = 0; mi < MI; mi++)
#pragma unroll
        for (int ni = 0; ni < NI; ni++)
#pragma unroll
            for (int r = 0; r < 4; r++) cfr[mi][ni][r] = 0.f;

    constexpr int A4 = BM * BK / 4;
    constexpr int B4 = BK * BN / 4;
    constexpr int ALD = A4 / THREADS;
    constexpr int BLD = B4 / THREADS;
    static_assert(ALD * THREADS == A4 && BLD * THREADS == B4, "load mapping");

    auto issue = [&](int it, int buf) {
        const int kb = kBeg + it * BK;
        float* as = As + buf * BM * BKP;
        float* bs = Bs + buf * BK * BNP;
#pragma unroll
        for (int i = 0; i < ALD; i++) {
            int j = tid + i * THREADS;
            int m = j / (BK / 4), kq = j % (BK / 4);
            cp_async16(as + m * BKP + kq * 4, A + (size_t)(m0 + m) * K + kb + kq * 4);
        }
#pragma unroll
        for (int i = 0; i < BLD; i++) {
            int j = tid + i * THREADS;
            int kr = j / (BN / 4), nq = j % (BN / 4);
            cp_async16(bs + kr * BNP + nq * 4, B + (size_t)(kb + kr) * N + n0 + nq * 4);
        }
        cp_commit();
    };

    auto compute = [&](int buf) {
        const float* as = As + buf * BM * BKP;
        const float* bs = Bs + buf * BK * BNP;
#pragma unroll
        for (int kc = 0; kc < BK; kc += 16) {
            unsigned af[MI][4], bf[NI][2];
#pragma unroll
            for (int mi = 0; mi < MI; mi++) {
                int r = wm + mi * 16 + gid;
                float2 p0 = *(const float2*)(as + (size_t)(r)     * BKP + kc + 2 * tig);
                float2 p1 = *(const float2*)(as + (size_t)(r + 8) * BKP + kc + 2 * tig);
                float2 p2 = *(const float2*)(as + (size_t)(r)     * BKP + kc + 2 * tig + 8);
                float2 p3 = *(const float2*)(as + (size_t)(r + 8) * BKP + kc + 2 * tig + 8);
                af[mi][0] = pack_h2(p0.x, p0.y);
                af[mi][1] = pack_h2(p1.x, p1.y);
                af[mi][2] = pack_h2(p2.x, p2.y);
                af[mi][3] = pack_h2(p3.x, p3.y);
            }
#pragma unroll
            for (int ni = 0; ni < NI; ni++) {
                int cn = wn + ni * 8 + gid;
                bf[ni][0] = pack_h2(bs[(kc + 2 * tig)     * BNP + cn],
                                    bs[(kc + 2 * tig + 1) * BNP + cn]);
                bf[ni][1] = pack_h2(bs[(kc + 2 * tig + 8) * BNP + cn],
                                    bs[(kc + 2 * tig + 9) * BNP + cn]);
            }
#pragma unroll
            for (int mi = 0; mi < MI; mi++)
#pragma unroll
                for (int ni = 0; ni < NI; ni++)
                    mma_f16(cfr[mi][ni], af[mi], bf[ni]);
        }
    };

    const int nIter = kPer / BK;
#pragma unroll
    for (int s = 0; s < STAGES - 1; s++) issue(s, s);
    for (int it = 0; it < nIter; ++it) {
        cp_wait<STAGES - 2>();
        __syncthreads();
        const int nx = it + STAGES - 1;
        if (nx < nIter) issue(nx, nx % STAGES); else cp_commit();
        compute(it % STAGES);
    }

#pragma unroll
    for (int mi = 0; mi < MI; mi++) {
#pragma unroll
        for (int ni = 0; ni < NI; ni++) {
            int row = m0 + wm + mi * 16 + gid;
            int col = n0 + wn + ni * 8 + tig * 2;
            *(float2*)(&Cout[(size_t)row * N + col]) =
                make_float2(cfr[mi][ni][0], cfr[mi][ni][1]);
            *(float2*)(&Cout[(size_t)(row + 8) * N + col]) =
                make_float2(cfr[mi][ni][2], cfr[mi][ni][3]);
        }
    }
}

// ---------------- reductions / fused epilogues -------------------------------
__global__ void reduce_ws(const float* __restrict__ part, float* __restrict__ out,
                          int mn, int W, int S) {
    int i = (blockIdx.x * blockDim.x + threadIdx.x) * 4;
    if (i >= W * mn) return;
    int w = i / mn, e = i % mn;
    const float* p = part + (size_t)(w * S) * mn + e;
    float4 acc = *(const float4*)p;
    for (int zx = 1; zx < S; zx++) {
        float4 t = *(const float4*)(p + (size_t)zx * mn);
        acc.x += t.x; acc.y += t.y; acc.z += t.z; acc.w += t.w;
    }
    *(float4*)(out + i) = acc;
}

__global__ void reduce_qkv_scatter(const float* __restrict__ part,
                                   float* __restrict__ qbuf,
                                   float* __restrict__ cache,
                                   const int* __restrict__ tokp, int S) {
    int i = (blockIdx.x * blockDim.x + threadIdx.x) * 4;
    if (i >= 3 * BB * EE) return;
    const int w = i / (BB * EE);
    const int e = i % (BB * EE);
    const float* p = part + (size_t)(w * S) * (BB * EE) + e;
    float4 acc = *(const float4*)p;
    for (int zx = 1; zx < S; zx++) {
        float4 t = *(const float4*)(p + (size_t)zx * (BB * EE));
        acc.x += t.x; acc.y += t.y; acc.z += t.z; acc.w += t.w;
    }
    const int tok = *tokp;
    const int b = e / EE, c = e % EE;
    if (w == 0)      *(float4*)(&cache[((size_t)b * II + tok) * EE + c]) = acc;
    else if (w == 1) *(float4*)(&cache[((size_t)(BB + b) * II + tok) * EE + c]) = acc;
    else             *(float4*)(&qbuf[e]) = acc;
}

__device__ __forceinline__ float gelu_exact(float x) {
    return 0.5f * x * (1.0f + erff(x * 0.70710678118654752f));
}

__global__ void ln_reduce_kernel(const float* __restrict__ part, int S,
                                 const float* __restrict__ scale,
                                 const float* __restrict__ bias,
                                 const float* __restrict__ residual,
                                 float* __restrict__ out) {
    __shared__ float buf[EE];
    __shared__ float rs[8], rs2[8];
    const int row = blockIdx.x;
    const int t = threadIdx.x;
    float s = 0.f, s2 = 0.f;
    for (int c = t * 4; c < EE; c += 256 * 4) {
        const float* p = part + (size_t)row * EE + c;
        float4 acc = *(const float4*)p;
        for (int zx = 1; zx < S; zx++) {
            float4 v = *(const float4*)(p + (size_t)zx * BB * EE);
            acc.x += v.x; acc.y += v.y; acc.z += v.z; acc.w += v.w;
        }
        *(float4*)(&buf[c]) = acc;
        s  += acc.x + acc.y + acc.z + acc.w;
        s2 += acc.x*acc.x + acc.y*acc.y + acc.z*acc.z + acc.w*acc.w;
    }
#pragma unroll
    for (int o = 16; o; o >>= 1) {
        s  += __shfl_down_sync(0xffffffffu, s, o);
        s2 += __shfl_down_sync(0xffffffffu, s2, o);
    }
    const int w = t >> 5;
    if ((t & 31) == 0) { rs[w] = s; rs2[w] = s2; }
    __syncthreads();
    if (t == 0) {
        float a = 0.f, b = 0.f;
        for (int i = 0; i < 8; i++) { a += rs[i]; b += rs2[i]; }
        rs[0] = a; rs2[0] = b;
    }
    __syncthreads();
    const float mu  = rs[0] / (float)EE;
    const float var = rs2[0] / (float)EE - mu * mu;
    const float inv = rsqrtf(var + 1e-6f);
    for (int c = t; c < EE; c += 256) {
        out[(size_t)row * EE + c] = (buf[c] - mu) * inv * scale[c] + bias[c]
                                    + residual[(size_t)row * EE + c];
    }
}

__global__ void ln_glu_kernel(const float* __restrict__ part, int S,
                              const float* __restrict__ scale,
                              const float* __restrict__ bias,
                              float* __restrict__ out) {
    __shared__ float buf[GG];
    __shared__ float rs[8], rs2[8];
    const int row = blockIdx.x;
    const int t = threadIdx.x;
    float s = 0.f, s2 = 0.f;
    for (int c = t * 4; c < GG; c += 256 * 4) {
        const float* pa = part + (size_t)row * GG + c;
        const float* pb = pa + (size_t)S * BB * GG;
        float4 a = *(const float4*)pa;
        float4 b = *(const float4*)pb;
        for (int zx = 1; zx < S; zx++) {
            float4 ta = *(const float4*)(pa + (size_t)zx * BB * GG);
            float4 tb = *(const float4*)(pb + (size_t)zx * BB * GG);
            a.x += ta.x; a.y += ta.y; a.z += ta.z; a.w += ta.w;
            b.x += tb.x; b.y += tb.y; b.z += tb.z; b.w += tb.w;
        }
        float4 r;
        r.x = gelu_exact(a.x) * b.x;
        r.y = gelu_exact(a.y) * b.y;
        r.z = gelu_exact(a.z) * b.z;
        r.w = gelu_exact(a.w) * b.w;
        *(float4*)(&buf[c]) = r;
        s  += r.x + r.y + r.z + r.w;
        s2 += r.x*r.x + r.y*r.y + r.z*r.z + r.w*r.w;
    }
#pragma unroll
    for (int o = 16; o; o >>= 1) {
        s  += __shfl_down_sync(0xffffffffu, s, o);
        s2 += __shfl_down_sync(0xffffffffu, s2, o);
    }
    const int w = t >> 5;
    if ((t & 31) == 0) { rs[w] = s; rs2[w] = s2; }
    __syncthreads();
    if (t == 0) {
        float a = 0.f, b = 0.f;
        for (int i = 0; i < 8; i++) { a += rs[i]; b += rs2[i]; }
        rs[0] = a; rs2[0] = b;
    }
    __syncthreads();
    const float mu  = rs[0] / (float)GG;
    const float var = rs2[0] / (float)GG - mu * mu;
    const float inv = rsqrtf(var + 1e-6f);
    for (int c = t; c < GG; c += 256) {
        out[(size_t)row * GG + c] = (buf[c] - mu) * inv * scale[c] + bias[c];
    }
}

__global__ void reduce_add(const float* __restrict__ part, const float* __restrict__ res,
                           float* __restrict__ out, int mn, int S) {
    int i = (blockIdx.x * blockDim.x + threadIdx.x) * 4;
    if (i >= mn) return;
    float4 acc = *(const float4*)(part + i);
    for (int zx = 1; zx < S; zx++) {
        float4 t = *(const float4*)(part + (size_t)zx * mn + i);
        acc.x += t.x; acc.y += t.y; acc.z += t.z; acc.w += t.w;
    }
    float4 r = *(const float4*)(res + i);
    acc.x += r.x; acc.y += r.y; acc.z += r.z; acc.w += r.w;
    *(float4*)(out + i) = acc;
}

// ---------------- LayerNorm ---------------------------------------------------
__global__ void ln_kernel(const float* __restrict__ in,
                          const float* __restrict__ scale,
                          const float* __restrict__ bias,
                          const float* __restrict__ residual,
                          float* __restrict__ out, int cols) {
    const int row = blockIdx.x;
    const float* x = in + (size_t)row * cols;
    float s = 0.f, s2 = 0.f;
    for (int c = threadIdx.x; c < cols; c += 256) {
        float v = x[c]; s += v; s2 += v * v;
    }
#pragma unroll
    for (int o = 16; o; o >>= 1) {
        s  += __shfl_down_sync(0xffffffffu, s, o);
        s2 += __shfl_down_sync(0xffffffffu, s2, o);
    }
    __shared__ float rs[8], rs2[8];
    const int w = threadIdx.x >> 5;
    if ((threadIdx.x & 31) == 0) { rs[w] = s; rs2[w] = s2; }
    __syncthreads();
    if (threadIdx.x == 0) {
        float a = 0.f, b = 0.f;
        for (int i = 0; i < 8; i++) { a += rs[i]; b += rs2[i]; }
        rs[0] = a; rs2[0] = b;
    }
    __syncthreads();
    const float mu  = rs[0] / (float)cols;
    const float var = rs2[0] / (float)cols - mu * mu;
    const float inv = rsqrtf(var + 1e-6f);
    for (int c = threadIdx.x; c < cols; c += 256) {
        float y = (x[c] - mu) * inv;
        if (scale)    y *= scale[c];
        if (bias)     y += bias[c];
        if (residual) y += residual[(size_t)row * cols + c];
        out[(size_t)row * cols + c] = y;
    }
}

// ---------------- self-attention (Q=1), smem-staged K for coalescing --------
__global__ void self_attn_kernel(const float* __restrict__ q,
                                 const float* __restrict__ cache,
                                 const int* __restrict__ tokp,
                                 float* __restrict__ out) {
    const int bh = blockIdx.x;
    const int b = bh >> 5, h = bh & 31;
    int nk = *tokp + 1;
    if (nk > II) nk = II;
    __shared__ float sq[DD];
    __shared__ float ks[64 * 65];
    __shared__ float sl[II];
    __shared__ float red[4 * DD];
    __shared__ float sume[4];
    __shared__ float smax;
    const int t = threadIdx.x;   // 256
    if (t < DD) sq[t] = q[(size_t)b * EE + h * DD + t] * 0.125f;
    __syncthreads();
    // K phase: stage chunks of 64 keys coalesced, then dot from smem
    for (int ck = 0; ck < nk; ck += 64) {
        int cnt = nk - ck; if (cnt > 64) cnt = 64;
        for (int j = t; j < cnt * 64; j += 256) {
            int row = j >> 6, c = j & 63;
            ks[row * 65 + c] = cache[((size_t)b * II + ck + row) * EE + h * DD + c];
        }
        __syncthreads();
        if (t < cnt) {
            float s = 0.f;
#pragma unroll 16
            for (int c = 0; c < DD; c++) s += sq[c] * ks[t * 65 + c];
            sl[ck + t] = s;
        }
        __syncthreads();
    }
    if (t < 32) {
        float m = -1e30f;
        for (int k = t; k < nk; k += 32) m = fmaxf(m, sl[k]);
#pragma unroll
        for (int o = 16; o; o >>= 1) m = fmaxf(m, __shfl_down_sync(0xffffffffu, m, o));
        if (t == 0) smax = m;
    }
    __syncthreads();
    const float m = smax;
    const int g = t >> 6, d = t & 63;
    const int kpg = (nk + 3) >> 2;
    const int k0 = g * kpg;
    int k1 = k0 + kpg; if (k1 > nk) k1 = nk;
    const float* vb = cache + (size_t)(BB + b) * II * EE + h * DD + d;
    float se = 0.f, acc = 0.f;
    for (int k = k0; k < k1; k++) {
        float e = __expf(sl[k] - m);
        se += e;
        acc += e * vb[(size_t)k * EE];
    }
    red[t] = acc;
    if (d == 0) sume[g] = se;
    __syncthreads();
    if (t < DD) {
        float a = red[t] + red[DD + t] + red[2 * DD + t] + red[3 * DD + t];
        float s = sume[0] + sume[1] + sume[2] + sume[3];
        out[(size_t)b * EE + h * DD + t] = a / s;
    }
}

// ---------------- cross-attention (T=64), 256-thread cooperative -----------
__global__ void cross_attn_kernel(const float* __restrict__ q,
                                  const float* __restrict__ ek,
                                  const float* __restrict__ ev,
                                  const int* __restrict__ mask,
                                  float* __restrict__ out) {
    const int bh = blockIdx.x;
    const int b = bh >> 5, h = bh & 31;
    __shared__ float sq[DD];
    __shared__ float sl[TT];
    __shared__ float red[4 * DD];
    __shared__ float sume[4];
    __shared__ float smax;
    const int t = threadIdx.x;   // 256
    if (t < DD) sq[t] = q[(size_t)b * EE + h * DD + t] * 0.125f;
    __syncthreads();
    if (t < TT) {
        const float4* kp = (const float4*)(ek + ((size_t)b * TT + t) * EE + h * DD);
        float s = 0.f;
#pragma unroll
        for (int c = 0; c < DD / 4; c++) {
            float4 v = kp[c];
            s += sq[4*c] * v.x + sq[4*c+1] * v.y + sq[4*c+2] * v.z + sq[4*c+3] * v.w;
        }
        s += (1.0f - (float)mask[b * TT + t]) * -1e12f;
        sl[t] = s;
    }
    __syncthreads();
    if (t < 32) {
        float m = fmaxf(sl[t], sl[t + 32]);
#pragma unroll
        for (int o = 16; o; o >>= 1) m = fmaxf(m, __shfl_down_sync(0xffffffffu, m, o));
        if (t == 0) smax = m;
    }
    __syncthreads();
    const float m = smax;
    const int g = t >> 6, d = t & 63;
    const int k0 = g * (TT / 4);
    const float* vb = ev + (size_t)b * TT * EE + h * DD + d;
    float se = 0.f, acc = 0.f;
    for (int k = k0; k < k0 + TT / 4; k++) {
        float e = __expf(sl[k] - m);
        se += e;
        acc += e * vb[(size_t)k * EE];
    }
    red[t] = acc;
    if (d == 0) sume[g] = se;
    __syncthreads();
    if (t < DD) {
        float a = red[t] + red[DD + t] + red[2 * DD + t] + red[3 * DD + t];
        float s = sume[0] + sume[1] + sume[2] + sume[3];
        out[(size_t)b * EE + h * DD + t] = a / s;
    }
}

// ---------------------------------------------------------------------------
#define GEMM_SMALL_T gemm_pipe<64,64,32,32,16,256,4>
#define SMEM_SMALL   ((4*(64*36) + 4*(32*72)) * 4)
#define SMEM_H16     ((3*(256*40) + 3*(32*136)) * 2)

extern "C" void kernel_launch(void* const* d_in, const int* in_sizes, int n_in,
                              void* d_out, int out_size) {
    (void)in_sizes; (void)n_in; (void)out_size;
    const float* ds_in        = (const float*)d_in[0];
    const float* enc          = (const float*)d_in[1];
    const float* attn_in      = (const float*)d_in[2];
    const int*   attn_mask    = (const int*)  d_in[3];
    const int*   token_index  = (const int*)  d_in[4];
    const float* ln_pre_sa_b  = (const float*)d_in[5];
    const float* q_sa         = (const float*)d_in[6];
    const float* k_sa         = (const float*)d_in[7];
    const float* v_sa         = (const float*)d_in[8];
    const float* o_sa         = (const float*)d_in[9];
    const float* ln_sa_s      = (const float*)d_in[10];
    const float* ln_sa_b      = (const float*)d_in[11];
    const float* ln_pre_ca_b  = (const float*)d_in[12];
    const float* q_ca         = (const float*)d_in[13];
    const float* k_ca         = (const float*)d_in[14];
    const float* v_ca         = (const float*)d_in[15];
    const float* o_ca         = (const float*)d_in[16];
    const float* ln_ca_s      = (const float*)d_in[17];
    const float* ln_ca_b      = (const float*)d_in[18];
    const float* glu_ln0_b    = (const float*)d_in[19];
    const float* fc0_w        = (const float*)d_in[20];
    const float* fc1_w        = (const float*)d_in[21];
    const float* glu_ln1_s    = (const float*)d_in[22];
    const float* glu_ln1_b    = (const float*)d_in[23];
    const float* fc2_w        = (const float*)d_in[24];

    float* out_dec  = (float*)d_out;
    float* out_attn = out_dec + (size_t)BB * EE;

    float *x0, *q, *attn, *ds1, *ds2, *x1, *q1, *ekv, *z2, *part;
    __half *enc_h, *wk_h, *wv_h;
    cudaGetSymbolAddress((void**)&x0,   g_x0);
    cudaGetSymbolAddress((void**)&q,    g_q);
    cudaGetSymbolAddress((void**)&attn, g_attn);
    cudaGetSymbolAddress((void**)&ds1,  g_ds1);
    cudaGetSymbolAddress((void**)&ds2,  g_ds2);
    cudaGetSymbolAddress((void**)&x1,   g_x1);
    cudaGetSymbolAddress((void**)&q1,   g_q1);
    cudaGetSymbolAddress((void**)&ekv,  g_ekv);
    cudaGetSymbolAddress((void**)&z2,   g_z2);
    cudaGetSymbolAddress((void**)&part, g_part);
    cudaGetSymbolAddress((void**)&enc_h, g_enc_h);
    cudaGetSymbolAddress((void**)&wk_h,  g_wk_h);
    cudaGetSymbolAddress((void**)&wv_h,  g_wv_h);

    cudaFuncSetAttribute(GEMM_SMALL_T, cudaFuncAttributeMaxDynamicSharedMemorySize, SMEM_SMALL);
    cudaFuncSetAttribute(gemm_h16,     cudaFuncAttributeMaxDynamicSharedMemorySize, SMEM_H16);

    float* ek = ekv;
    float* ev = ekv + (size_t)BB * TT * EE;

    // ---- persistent handles (created once; see round-7 note) ---------------
    static cudaStream_t sA = nullptr, sB = nullptr;
    static cudaEvent_t eFork = nullptr, eCopy = nullptr, eGemm = nullptr;
    if (sA == nullptr) {
        cudaStreamCreateWithFlags(&sA, cudaStreamNonBlocking);
        cudaStreamCreateWithFlags(&sB, cudaStreamNonBlocking);
        cudaEventCreateWithFlags(&eFork, cudaEventDisableTiming);
        cudaEventCreateWithFlags(&eCopy, cudaEventDisableTiming);
        cudaEventCreateWithFlags(&eGemm, cudaEventDisableTiming);
    }

    cudaEventRecord(eFork, 0);
    cudaStreamWaitEvent(sA, eFork, 0);
    cudaStreamWaitEvent(sB, eFork, 0);

    // branch A: KV-cache pass-through copy (CE)
    cudaMemcpyAsync(out_attn, attn_in, (size_t)2 * BB * II * EE * sizeof(float),
                    cudaMemcpyDeviceToDevice, sA);
    cudaEventRecord(eCopy, sA);

    // branch B: f32->f16 conversion + big ek/ev GEMM (256x128 tiles)
    {
        const int na = BB * TT * EE, nb = EE * EE, nc = EE * EE;
        const int tot = na + nb + nc;
        f2h3_kernel<<<(tot / 8 + 255) / 256, 256, 0, sB>>>(enc, enc_h, na,
                                                           k_ca, wk_h, nb,
                                                           v_ca, wv_h, nc);
        gemm_h16<<<dim3(EE / 128, (BB * TT) / 256, 2), 512, SMEM_H16, sB>>>(
            enc_h, wk_h, wv_h, ekv, BB * TT, EE, EE);
        cudaEventRecord(eGemm, sB);
    }

    // ---- main chain: self-attention block ----------------------------------
    ln_kernel<<<BB, 256>>>(ds_in, nullptr, ln_pre_sa_b, nullptr, x0, EE);
    GEMM_SMALL_T<<<dim3(EE/64, 1, 3*8), 256, SMEM_SMALL>>>(x0, k_sa, v_sa, q_sa,
                                                           part, BB, EE, EE, 8);
    cudaStreamWaitEvent(0, eCopy, 0);
    reduce_qkv_scatter<<<(3*BB*EE/4 + 255)/256, 256>>>(part, q, out_attn, token_index, 8);
    self_attn_kernel<<<BB*HH, 256>>>(q, out_attn, token_index, attn);
    GEMM_SMALL_T<<<dim3(EE/64, 1, 8), 256, SMEM_SMALL>>>(attn, o_sa, o_sa, o_sa,
                                                         part, BB, EE, EE, 8);
    ln_reduce_kernel<<<BB, 256>>>(part, 8, ln_sa_s, ln_sa_b, ds_in, ds1);

    // ---- cross-attention block ----------------------------------------------
    ln_kernel<<<BB, 256>>>(ds1, nullptr, ln_pre_ca_b, nullptr, x1, EE);
    GEMM_SMALL_T<<<dim3(EE/64, 1, 8), 256, SMEM_SMALL>>>(x1, q_ca, q_ca, q_ca,
                                                         part, BB, EE, EE, 8);
    reduce_ws<<<(BB*EE/4 + 255)/256, 256>>>(part, q1, BB*EE, 1, 8);
    cudaStreamWaitEvent(0, eGemm, 0);
    cross_attn_kernel<<<BB*HH, 256>>>(q1, ek, ev, attn_mask, attn);
    GEMM_SMALL_T<<<dim3(EE/64, 1, 8), 256, SMEM_SMALL>>>(attn, o_ca, o_ca, o_ca,
                                                         part, BB, EE, EE, 8);
    ln_reduce_kernel<<<BB, 256>>>(part, 8, ln_ca_s, ln_ca_b, ds1, ds2);

    // ---- GLU feed-forward block ---------------------------------------------
    ln_kernel<<<BB, 256>>>(ds2, nullptr, glu_ln0_b, nullptr, x0, EE);
    GEMM_SMALL_T<<<dim3(GG/64, 1, 2*4), 256, SMEM_SMALL>>>(x0, fc0_w, fc1_w, fc1_w,
                                                           part, BB, GG, EE, 4);
    ln_glu_kernel<<<BB, 256>>>(part, 4, glu_ln1_s, glu_ln1_b, z2);
    GEMM_SMALL_T<<<dim3(EE/64, 1, 8), 256, SMEM_SMALL>>>(z2, fc2_w, fc2_w, fc2_w,
                                                         part, BB, EE, GG, 8);
    reduce_add<<<(BB*EE/4 + 255)/256, 256>>>(part, ds2, out_dec, BB*EE, 8);
}

// round 11
// speedup vs baseline: 1.7231x; 1.0782x over previous
#include <cuda_runtime.h>
#include <cuda_fp16.h>
#include <math.h>

#define BB 64     // batch
#define TT 64     // encoder tokens
#define EE 2048   // embed dim
#define GG 4096   // GLU hidden
#define II 256    // image token count (KV cache length)
#define HH 32     // heads
#define DD 64     // head dim

// ---------------- scratch (device globals; no runtime allocation) ----------
__device__ float g_x0  [BB * EE];
__device__ float g_q   [BB * EE];
__device__ float g_attn[BB * EE];
__device__ float g_ds1 [BB * EE];
__device__ float g_ds2 [BB * EE];
__device__ float g_x1  [BB * EE];
__device__ float g_q1  [BB * EE];
__device__ float g_ekv [2 * BB * TT * EE];  // ek then ev
__device__ float g_z2  [BB * GG];
__device__ float g_part[12 * BB * GG];      // split-K / multi-weight partials
__device__ __align__(16) __half g_enc_h[BB * TT * EE];
__device__ __align__(16) __half g_wk_h [EE * EE];
__device__ __align__(16) __half g_wv_h [EE * EE];

// ---------------- fp16 / cp.async / ldmatrix helpers ------------------------
__device__ __forceinline__ unsigned pack_h2(float lo, float hi) {
    __half2 h = __floats2half2_rn(lo, hi);
    return *(unsigned*)&h;
}
__device__ __forceinline__ void mma_f16(float c[4], const unsigned a[4], const unsigned b[2]) {
    asm volatile(
        "mma.sync.aligned.m16n8k16.row.col.f32.f16.f16.f32 "
        "{%0,%1,%2,%3}, {%4,%5,%6,%7}, {%8,%9}, {%0,%1,%2,%3};"
        : "+f"(c[0]), "+f"(c[1]), "+f"(c[2]), "+f"(c[3])
        : "r"(a[0]), "r"(a[1]), "r"(a[2]), "r"(a[3]), "r"(b[0]), "r"(b[1]));
}
__device__ __forceinline__ void cp_async16(void* sptr, const void* gptr) {
    unsigned sa = (unsigned)__cvta_generic_to_shared(sptr);
    asm volatile("cp.async.cg.shared.global [%0], [%1], 16;\n" :: "r"(sa), "l"(gptr));
}
__device__ __forceinline__ void cp_commit() {
    asm volatile("cp.async.commit_group;\n" ::: "memory");
}
template<int N>
__device__ __forceinline__ void cp_wait() {
    asm volatile("cp.async.wait_group %0;\n" :: "n"(N) : "memory");
}
__device__ __forceinline__ void ldsm_x4(unsigned r[4], unsigned saddr) {
    asm volatile("ldmatrix.sync.aligned.m8n8.x4.shared.b16 {%0,%1,%2,%3}, [%4];"
                 : "=r"(r[0]), "=r"(r[1]), "=r"(r[2]), "=r"(r[3]) : "r"(saddr));
}
__device__ __forceinline__ void ldsm_x4t(unsigned r[4], unsigned saddr) {
    asm volatile("ldmatrix.sync.aligned.m8n8.x4.trans.shared.b16 {%0,%1,%2,%3}, [%4];"
                 : "=r"(r[0]), "=r"(r[1]), "=r"(r[2]), "=r"(r[3]) : "r"(saddr));
}

// ---------------- f32 -> f16 conversion (3 regions, one launch) ------------
__global__ void f2h3_kernel(const float* __restrict__ a, __half* __restrict__ ah, int na,
                            const float* __restrict__ b, __half* __restrict__ bh, int nb,
                            const float* __restrict__ c, __half* __restrict__ ch, int nc) {
    int i = (blockIdx.x * blockDim.x + threadIdx.x) * 8;
    if (i >= na + nb + nc) return;
    const float* src; __half* dst; int off;
    if (i < na)           { src = a; dst = ah; off = i; }
    else if (i < na + nb) { src = b; dst = bh; off = i - na; }
    else                  { src = c; dst = ch; off = i - na - nb; }
    float4 v0 = *(const float4*)(src + off);
    float4 v1 = *(const float4*)(src + off + 4);
    __half2 h0 = __floats2half2_rn(v0.x, v0.y);
    __half2 h1 = __floats2half2_rn(v0.z, v0.w);
    __half2 h2 = __floats2half2_rn(v1.x, v1.y);
    __half2 h3 = __floats2half2_rn(v1.z, v1.w);
    uint4 o = make_uint4(*(unsigned*)&h0, *(unsigned*)&h1, *(unsigned*)&h2, *(unsigned*)&h3);
    *(uint4*)(dst + off) = o;
}

// ---------------- fp16-native big GEMM (round-7 config: 128x128x32, 4 st) ---
__global__ __launch_bounds__(256)
void gemm_h16(const __half* __restrict__ A, const __half* __restrict__ B0,
              const __half* __restrict__ B1, float* __restrict__ C,
              int M, int N, int K) {
    constexpr int BM = 128, BN = 128, BK = 32, STAGES = 4, THREADS = 256;
    constexpr int BKP = BK + 8;
    constexpr int BNP = BN + 8;
    extern __shared__ char sm_[];
    __half* As = (__half*)sm_;
    __half* Bs = As + STAGES * BM * BKP;

    const __half* B = blockIdx.z ? B1 : B0;
    float* Cout = C + (size_t)blockIdx.z * M * N;
    const int n0 = blockIdx.x * BN;
    const int m0 = blockIdx.y * BM;
    const int tid = threadIdx.x;
    const int lane = tid & 31;
    const int warp = tid >> 5;
    const int wm = (warp >> 2) * 64;
    const int wn = (warp & 3) * 32;
    const int gid = lane >> 2, tig = lane & 3;

    float cfr[4][4][4];
#pragma unroll
    for (int mi = 0; mi < 4; mi++)
#pragma unroll
        for (int ni = 0; ni < 4; ni++)
#pragma unroll
            for (int r = 0; r < 4; r++) cfr[mi][ni][r] = 0.f;

    auto issue = [&](int it, int buf) {
        const int kb = it * BK;
        __half* as = As + buf * BM * BKP;
        __half* bs = Bs + buf * BK * BNP;
#pragma unroll
        for (int i = 0; i < 2; i++) {
            int j = tid + i * THREADS;
            int row = j >> 2, kq = (j & 3) * 8;
            cp_async16(as + row * BKP + kq, A + (size_t)(m0 + row) * K + kb + kq);
        }
#pragma unroll
        for (int i = 0; i < 2; i++) {
            int j = tid + i * THREADS;
            int kr = j >> 4, nq = (j & 15) * 8;
            cp_async16(bs + kr * BNP + nq, B + (size_t)(kb + kr) * N + n0 + nq);
        }
        cp_commit();
    };

    unsigned asb = (unsigned)__cvta_generic_to_shared(As);
    unsigned bsb = (unsigned)__cvta_generic_to_shared(Bs);
    const int l8 = lane & 7, lb = (lane >> 3) & 1, lc = lane >> 4;
    const unsigned aoff = ((wm + lb * 8 + l8) * BKP + lc * 8) * 2;
    const unsigned boff = ((lb * 8 + l8) * BNP + wn + lc * 8) * 2;

    auto compute = [&](int buf) {
        unsigned ab = asb + buf * BM * BKP * 2 + aoff;
        unsigned bb = bsb + buf * BK * BNP * 2 + boff;
#pragma unroll
        for (int kc = 0; kc < BK; kc += 16) {
            unsigned af[4][4], bf[4][2];
#pragma unroll
            for (int mi = 0; mi < 4; mi++)
                ldsm_x4(af[mi], ab + (mi * 16 * BKP + kc) * 2);
#pragma unroll
            for (int p = 0; p < 2; p++) {
                unsigned r[4];
                ldsm_x4t(r, bb + (kc * BNP + p * 16) * 2);
                bf[2 * p][0] = r[0]; bf[2 * p][1] = r[1];
                bf[2 * p + 1][0] = r[2]; bf[2 * p + 1][1] = r[3];
            }
#pragma unroll
            for (int mi = 0; mi < 4; mi++)
#pragma unroll
                for (int ni = 0; ni < 4; ni++)
                    mma_f16(cfr[mi][ni], af[mi], bf[ni]);
        }
    };

    const int nIter = K / BK;
#pragma unroll
    for (int s = 0; s < STAGES - 1; s++) issue(s, s);
    for (int it = 0; it < nIter; ++it) {
        cp_wait<STAGES - 2>();
        __syncthreads();
        const int nx = it + STAGES - 1;
        if (nx < nIter) issue(nx, nx % STAGES); else cp_commit();
        compute(it % STAGES);
    }

#pragma unroll
    for (int mi = 0; mi < 4; mi++) {
#pragma unroll
        for (int ni = 0; ni < 4; ni++) {
            int row = m0 + wm + mi * 16 + gid;
            int col = n0 + wn + ni * 8 + tig * 2;
            *(float2*)(&Cout[(size_t)row * N + col]) =
                make_float2(cfr[mi][ni][0], cfr[mi][ni][1]);
            *(float2*)(&Cout[(size_t)(row + 8) * N + col]) =
                make_float2(cfr[mi][ni][2], cfr[mi][ni][3]);
        }
    }
}

// ---------------- pipelined GEMM for small (M=64) GEMMs (f32 staged) -------
template<int BM, int BN, int BK, int WM, int WN, int THREADS, int STAGES>
__global__ __launch_bounds__(THREADS)
void gemm_pipe(const float* __restrict__ A,
               const float* __restrict__ B0, const float* __restrict__ B1,
               const float* __restrict__ B2,
               float* __restrict__ C, int M, int N, int K, int kSplit) {
    constexpr int BKP = BK + 4;
    constexpr int BNP = BN + 8;
    extern __shared__ float smem[];
    float* As = smem;
    float* Bs = smem + STAGES * BM * BKP;

    const int z = blockIdx.z;
    const int w = z / kSplit;
    const int zz = z % kSplit;
    const float* B = (w == 0) ? B0 : ((w == 1) ? B1 : B2);
    float* Cout = C + (size_t)z * M * N;
    const int kPer = K / kSplit;
    const int kBeg = zz * kPer;

    const int n0 = blockIdx.x * BN;
    const int m0 = blockIdx.y * BM;
    const int tid = threadIdx.x;
    const int lane = tid & 31;
    const int warp = tid >> 5;
    constexpr int WARPS_N = BN / WN;
    const int wm = (warp / WARPS_N) * WM;
    const int wn = (warp % WARPS_N) * WN;
    const int gid = lane >> 2;
    const int tig = lane & 3;
    constexpr int MI = WM / 16;
    constexpr int NI = WN / 8;

    float cfr[MI][NI][4];
#pragma unroll
    for (int mi = 0; mi < MI; mi++)
#pragma unroll
        for (int ni = 0; ni < NI; ni++)
#pragma unroll
            for (int r = 0; r < 4; r++) cfr[mi][ni][r] = 0.f;

    constexpr int A4 = BM * BK / 4;
    constexpr int B4 = BK * BN / 4;
    constexpr int ALD = A4 / THREADS;
    constexpr int BLD = B4 / THREADS;
    static_assert(ALD * THREADS == A4 && BLD * THREADS == B4, "load mapping");

    auto issue = [&](int it, int buf) {
        const int kb = kBeg + it * BK;
        float* as = As + buf * BM * BKP;
        float* bs = Bs + buf * BK * BNP;
#pragma unroll
        for (int i = 0; i < ALD; i++) {
            int j = tid + i * THREADS;
            int m = j / (BK / 4), kq = j % (BK / 4);
            cp_async16(as + m * BKP + kq * 4, A + (size_t)(m0 + m) * K + kb + kq * 4);
        }
#pragma unroll
        for (int i = 0; i < BLD; i++) {
            int j = tid + i * THREADS;
            int kr = j / (BN / 4), nq = j % (BN / 4);
            cp_async16(bs + kr * BNP + nq * 4, B + (size_t)(kb + kr) * N + n0 + nq * 4);
        }
        cp_commit();
    };

    auto compute = [&](int buf) {
        const float* as = As + buf * BM * BKP;
        const float* bs = Bs + buf * BK * BNP;
#pragma unroll
        for (int kc = 0; kc < BK; kc += 16) {
            unsigned af[MI][4], bf[NI][2];
#pragma unroll
            for (int mi = 0; mi < MI; mi++) {
                int r = wm + mi * 16 + gid;
                float2 p0 = *(const float2*)(as + (size_t)(r)     * BKP + kc + 2 * tig);
                float2 p1 = *(const float2*)(as + (size_t)(r + 8) * BKP + kc + 2 * tig);
                float2 p2 = *(const float2*)(as + (size_t)(r)     * BKP + kc + 2 * tig + 8);
                float2 p3 = *(const float2*)(as + (size_t)(r + 8) * BKP + kc + 2 * tig + 8);
                af[mi][0] = pack_h2(p0.x, p0.y);
                af[mi][1] = pack_h2(p1.x, p1.y);
                af[mi][2] = pack_h2(p2.x, p2.y);
                af[mi][3] = pack_h2(p3.x, p3.y);
            }
#pragma unroll
            for (int ni = 0; ni < NI; ni++) {
                int cn = wn + ni * 8 + gid;
                bf[ni][0] = pack_h2(bs[(kc + 2 * tig)     * BNP + cn],
                                    bs[(kc + 2 * tig + 1) * BNP + cn]);
                bf[ni][1] = pack_h2(bs[(kc + 2 * tig + 8) * BNP + cn],
                                    bs[(kc + 2 * tig + 9) * BNP + cn]);
            }
#pragma unroll
            for (int mi = 0; mi < MI; mi++)
#pragma unroll
                for (int ni = 0; ni < NI; ni++)
                    mma_f16(cfr[mi][ni], af[mi], bf[ni]);
        }
    };

    const int nIter = kPer / BK;
#pragma unroll
    for (int s = 0; s < STAGES - 1; s++) issue(s, s);
    for (int it = 0; it < nIter; ++it) {
        cp_wait<STAGES - 2>();
        __syncthreads();
        const int nx = it + STAGES - 1;
        if (nx < nIter) issue(nx, nx % STAGES); else cp_commit();
        compute(it % STAGES);
    }

#pragma unroll
    for (int mi = 0; mi < MI; mi++) {
#pragma unroll
        for (int ni = 0; ni < NI; ni++) {
            int row = m0 + wm + mi * 16 + gid;
            int col = n0 + wn + ni * 8 + tig * 2;
            *(float2*)(&Cout[(size_t)row * N + col]) =
                make_float2(cfr[mi][ni][0], cfr[mi][ni][1]);
            *(float2*)(&Cout[(size_t)(row + 8) * N + col]) =
                make_float2(cfr[mi][ni][2], cfr[mi][ni][3]);
        }
    }
}

// ---------------- reductions / fused epilogues (compile-time S!) ------------
__global__ void reduce_ws(const float* __restrict__ part, float* __restrict__ out,
                          int mn, int W, int S) {
    int i = (blockIdx.x * blockDim.x + threadIdx.x) * 4;
    if (i >= W * mn) return;
    int w = i / mn, e = i % mn;
    const float* p = part + (size_t)(w * S) * mn + e;
    float4 acc = *(const float4*)p;
    for (int zx = 1; zx < S; zx++) {
        float4 t = *(const float4*)(p + (size_t)zx * mn);
        acc.x += t.x; acc.y += t.y; acc.z += t.z; acc.w += t.w;
    }
    *(float4*)(out + i) = acc;
}

__global__ void reduce_qkv_scatter(const float* __restrict__ part,
                                   float* __restrict__ qbuf,
                                   float* __restrict__ cache,
                                   const int* __restrict__ tokp, int S) {
    int i = (blockIdx.x * blockDim.x + threadIdx.x) * 4;
    if (i >= 3 * BB * EE) return;
    const int w = i / (BB * EE);
    const int e = i % (BB * EE);
    const float* p = part + (size_t)(w * S) * (BB * EE) + e;
    float4 acc = *(const float4*)p;
    for (int zx = 1; zx < S; zx++) {
        float4 t = *(const float4*)(p + (size_t)zx * (BB * EE));
        acc.x += t.x; acc.y += t.y; acc.z += t.z; acc.w += t.w;
    }
    const int tok = *tokp;
    const int b = e / EE, c = e % EE;
    if (w == 0)      *(float4*)(&cache[((size_t)b * II + tok) * EE + c]) = acc;
    else if (w == 1) *(float4*)(&cache[((size_t)(BB + b) * II + tok) * EE + c]) = acc;
    else             *(float4*)(&qbuf[e]) = acc;
}

__device__ __forceinline__ float gelu_exact(float x) {
    return 0.5f * x * (1.0f + erff(x * 0.70710678118654752f));
}

// fused: val = sum_S part ; out = LN(val)*scale + bias + residual   (cols=EE)
// S is a TEMPLATE parameter -> the partial loads unroll and issue in parallel.
template<int S>
__global__ void ln_reduce_kernel(const float* __restrict__ part,
                                 const float* __restrict__ scale,
                                 const float* __restrict__ bias,
                                 const float* __restrict__ residual,
                                 float* __restrict__ out) {
    __shared__ float buf[EE];
    __shared__ float rs[8], rs2[8];
    const int row = blockIdx.x;
    const int t = threadIdx.x;  // 256
    float s = 0.f, s2 = 0.f;
#pragma unroll
    for (int c = t * 4; c < EE; c += 256 * 4) {
        const float* p = part + (size_t)row * EE + c;
        float4 v[S];
#pragma unroll
        for (int zx = 0; zx < S; zx++)
            v[zx] = *(const float4*)(p + (size_t)zx * BB * EE);
        float4 acc = v[0];
#pragma unroll
        for (int zx = 1; zx < S; zx++) {
            acc.x += v[zx].x; acc.y += v[zx].y; acc.z += v[zx].z; acc.w += v[zx].w;
        }
        *(float4*)(&buf[c]) = acc;
        s  += acc.x + acc.y + acc.z + acc.w;
        s2 += acc.x*acc.x + acc.y*acc.y + acc.z*acc.z + acc.w*acc.w;
    }
#pragma unroll
    for (int o = 16; o; o >>= 1) {
        s  += __shfl_down_sync(0xffffffffu, s, o);
        s2 += __shfl_down_sync(0xffffffffu, s2, o);
    }
    const int w = t >> 5;
    if ((t & 31) == 0) { rs[w] = s; rs2[w] = s2; }
    __syncthreads();
    if (t == 0) {
        float a = 0.f, b = 0.f;
        for (int i = 0; i < 8; i++) { a += rs[i]; b += rs2[i]; }
        rs[0] = a; rs2[0] = b;
    }
    __syncthreads();
    const float mu  = rs[0] / (float)EE;
    const float var = rs2[0] / (float)EE - mu * mu;
    const float inv = rsqrtf(var + 1e-6f);
    for (int c = t; c < EE; c += 256) {
        out[(size_t)row * EE + c] = (buf[c] - mu) * inv * scale[c] + bias[c]
                                    + residual[(size_t)row * EE + c];
    }
}

// fused: a=sum part[0..S), b=sum part[S..2S), w=gelu(a)*b ; out = LN(w)*s + b2
template<int S>
__global__ void ln_glu_kernel(const float* __restrict__ part,
                              const float* __restrict__ scale,
                              const float* __restrict__ bias,
                              float* __restrict__ out) {
    __shared__ float buf[GG];
    __shared__ float rs[8], rs2[8];
    const int row = blockIdx.x;
    const int t = threadIdx.x;  // 256
    float s = 0.f, s2 = 0.f;
#pragma unroll
    for (int c = t * 4; c < GG; c += 256 * 4) {
        const float* pa = part + (size_t)row * GG + c;
        const float* pb = pa + (size_t)S * BB * GG;
        float4 va[S], vb[S];
#pragma unroll
        for (int zx = 0; zx < S; zx++) {
            va[zx] = *(const float4*)(pa + (size_t)zx * BB * GG);
            vb[zx] = *(const float4*)(pb + (size_t)zx * BB * GG);
        }
        float4 a = va[0], b = vb[0];
#pragma unroll
        for (int zx = 1; zx < S; zx++) {
            a.x += va[zx].x; a.y += va[zx].y; a.z += va[zx].z; a.w += va[zx].w;
            b.x += vb[zx].x; b.y += vb[zx].y; b.z += vb[zx].z; b.w += vb[zx].w;
        }
        float4 r;
        r.x = gelu_exact(a.x) * b.x;
        r.y = gelu_exact(a.y) * b.y;
        r.z = gelu_exact(a.z) * b.z;
        r.w = gelu_exact(a.w) * b.w;
        *(float4*)(&buf[c]) = r;
        s  += r.x + r.y + r.z + r.w;
        s2 += r.x*r.x + r.y*r.y + r.z*r.z + r.w*r.w;
    }
#pragma unroll
    for (int o = 16; o; o >>= 1) {
        s  += __shfl_down_sync(0xffffffffu, s, o);
        s2 += __shfl_down_sync(0xffffffffu, s2, o);
    }
    const int w = t >> 5;
    if ((t & 31) == 0) { rs[w] = s; rs2[w] = s2; }
    __syncthreads();
    if (t == 0) {
        float a = 0.f, b = 0.f;
        for (int i = 0; i < 8; i++) { a += rs[i]; b += rs2[i]; }
        rs[0] = a; rs2[0] = b;
    }
    __syncthreads();
    const float mu  = rs[0] / (float)GG;
    const float var = rs2[0] / (float)GG - mu * mu;
    const float inv = rsqrtf(var + 1e-6f);
    for (int c = t; c < GG; c += 256) {
        out[(size_t)row * GG + c] = (buf[c] - mu) * inv * scale[c] + bias[c];
    }
}

// out = residual + sum_z part[z]   (compile-time S, unrolled parallel loads)
template<int S>
__global__ void reduce_add(const float* __restrict__ part, const float* __restrict__ res,
                           float* __restrict__ out, int mn) {
    int i = (blockIdx.x * blockDim.x + threadIdx.x) * 4;
    if (i >= mn) return;
    float4 v[S];
#pragma unroll
    for (int zx = 0; zx < S; zx++)
        v[zx] = *(const float4*)(part + (size_t)zx * mn + i);
    float4 acc = v[0];
#pragma unroll
    for (int zx = 1; zx < S; zx++) {
        acc.x += v[zx].x; acc.y += v[zx].y; acc.z += v[zx].z; acc.w += v[zx].w;
    }
    float4 r = *(const float4*)(res + i);
    acc.x += r.x; acc.y += r.y; acc.z += r.z; acc.w += r.w;
    *(float4*)(out + i) = acc;
}

// ---------------- LayerNorm ---------------------------------------------------
__global__ void ln_kernel(const float* __restrict__ in,
                          const float* __restrict__ scale,
                          const float* __restrict__ bias,
                          const float* __restrict__ residual,
                          float* __restrict__ out, int cols) {
    const int row = blockIdx.x;
    const float* x = in + (size_t)row * cols;
    float s = 0.f, s2 = 0.f;
    for (int c = threadIdx.x; c < cols; c += 256) {
        float v = x[c]; s += v; s2 += v * v;
    }
#pragma unroll
    for (int o = 16; o; o >>= 1) {
        s  += __shfl_down_sync(0xffffffffu, s, o);
        s2 += __shfl_down_sync(0xffffffffu, s2, o);
    }
    __shared__ float rs[8], rs2[8];
    const int w = threadIdx.x >> 5;
    if ((threadIdx.x & 31) == 0) { rs[w] = s; rs2[w] = s2; }
    __syncthreads();
    if (threadIdx.x == 0) {
        float a = 0.f, b = 0.f;
        for (int i = 0; i < 8; i++) { a += rs[i]; b += rs2[i]; }
        rs[0] = a; rs2[0] = b;
    }
    __syncthreads();
    const float mu  = rs[0] / (float)cols;
    const float var = rs2[0] / (float)cols - mu * mu;
    const float inv = rsqrtf(var + 1e-6f);
    for (int c = threadIdx.x; c < cols; c += 256) {
        float y = (x[c] - mu) * inv;
        if (scale)    y *= scale[c];
        if (bias)     y += bias[c];
        if (residual) y += residual[(size_t)row * cols + c];
        out[(size_t)row * cols + c] = y;
    }
}

// ---------------- self-attention (Q=1), 256-thread cooperative (round 7) ----
__global__ void self_attn_kernel(const float* __restrict__ q,
                                 const float* __restrict__ cache,
                                 const int* __restrict__ tokp,
                                 float* __restrict__ out) {
    const int bh = blockIdx.x;
    const int b = bh >> 5, h = bh & 31;
    int nk = *tokp + 1;
    if (nk > II) nk = II;
    __shared__ float sq[DD];
    __shared__ float sl[II];
    __shared__ float red[4 * DD];
    __shared__ float sume[4];
    __shared__ float smax;
    const int t = threadIdx.x;   // 256
    if (t < DD) sq[t] = q[(size_t)b * EE + h * DD + t] * 0.125f;
    __syncthreads();
    if (t < nk) {
        const float4* kp = (const float4*)(cache + ((size_t)b * II + t) * EE + h * DD);
        float s = 0.f;
#pragma unroll
        for (int c = 0; c < DD / 4; c++) {
            float4 v = kp[c];
            s += sq[4*c] * v.x + sq[4*c+1] * v.y + sq[4*c+2] * v.z + sq[4*c+3] * v.w;
        }
        sl[t] = s;
    }
    __syncthreads();
    if (t < 32) {
        float m = -1e30f;
        for (int k = t; k < nk; k += 32) m = fmaxf(m, sl[k]);
#pragma unroll
        for (int o = 16; o; o >>= 1) m = fmaxf(m, __shfl_down_sync(0xffffffffu, m, o));
        if (t == 0) smax = m;
    }
    __syncthreads();
    const float m = smax;
    const int g = t >> 6, d = t & 63;
    const int kpg = (nk + 3) >> 2;
    const int k0 = g * kpg;
    int k1 = k0 + kpg; if (k1 > nk) k1 = nk;
    const float* vb = cache + (size_t)(BB + b) * II * EE + h * DD + d;
    float se = 0.f, acc = 0.f;
    for (int k = k0; k < k1; k++) {
        float e = __expf(sl[k] - m);
        se += e;
        acc += e * vb[(size_t)k * EE];
    }
    red[t] = acc;
    if (d == 0) sume[g] = se;
    __syncthreads();
    if (t < DD) {
        float a = red[t] + red[DD + t] + red[2 * DD + t] + red[3 * DD + t];
        float s = sume[0] + sume[1] + sume[2] + sume[3];
        out[(size_t)b * EE + h * DD + t] = a / s;
    }
}

// ---------------- cross-attention (T=64), 256-thread cooperative -----------
__global__ void cross_attn_kernel(const float* __restrict__ q,
                                  const float* __restrict__ ek,
                                  const float* __restrict__ ev,
                                  const int* __restrict__ mask,
                                  float* __restrict__ out) {
    const int bh = blockIdx.x;
    const int b = bh >> 5, h = bh & 31;
    __shared__ float sq[DD];
    __shared__ float sl[TT];
    __shared__ float red[4 * DD];
    __shared__ float sume[4];
    __shared__ float smax;
    const int t = threadIdx.x;   // 256
    if (t < DD) sq[t] = q[(size_t)b * EE + h * DD + t] * 0.125f;
    __syncthreads();
    if (t < TT) {
        const float4* kp = (const float4*)(ek + ((size_t)b * TT + t) * EE + h * DD);
        float s = 0.f;
#pragma unroll
        for (int c = 0; c < DD / 4; c++) {
            float4 v = kp[c];
            s += sq[4*c] * v.x + sq[4*c+1] * v.y + sq[4*c+2] * v.z + sq[4*c+3] * v.w;
        }
        s += (1.0f - (float)mask[b * TT + t]) * -1e12f;
        sl[t] = s;
    }
    __syncthreads();
    if (t < 32) {
        float m = fmaxf(sl[t], sl[t + 32]);
#pragma unroll
        for (int o = 16; o; o >>= 1) m = fmaxf(m, __shfl_down_sync(0xffffffffu, m, o));
        if (t == 0) smax = m;
    }
    __syncthreads();
    const float m = smax;
    const int g = t >> 6, d = t & 63;
    const int k0 = g * (TT / 4);
    const float* vb = ev + (size_t)b * TT * EE + h * DD + d;
    float se = 0.f, acc = 0.f;
    for (int k = k0; k < k0 + TT / 4; k++) {
        float e = __expf(sl[k] - m);
        se += e;
        acc += e * vb[(size_t)k * EE];
    }
    red[t] = acc;
    if (d == 0) sume[g] = se;
    __syncthreads();
    if (t < DD) {
        float a = red[t] + red[DD + t] + red[2 * DD + t] + red[3 * DD + t];
        float s = sume[0] + sume[1] + sume[2] + sume[3];
        out[(size_t)b * EE + h * DD + t] = a / s;
    }
}

// ---------------------------------------------------------------------------
#define GEMM_SMALL_T gemm_pipe<64,64,32,32,16,256,4>
#define SMEM_SMALL   ((4*(64*36) + 4*(32*72)) * 4)
#define SMEM_H16     ((4*(128*40) + 4*(32*136)) * 2)

extern "C" void kernel_launch(void* const* d_in, const int* in_sizes, int n_in,
                              void* d_out, int out_size) {
    (void)in_sizes; (void)n_in; (void)out_size;
    const float* ds_in        = (const float*)d_in[0];
    const float* enc          = (const float*)d_in[1];
    const float* attn_in      = (const float*)d_in[2];
    const int*   attn_mask    = (const int*)  d_in[3];
    const int*   token_index  = (const int*)  d_in[4];
    const float* ln_pre_sa_b  = (const float*)d_in[5];
    const float* q_sa         = (const float*)d_in[6];
    const float* k_sa         = (const float*)d_in[7];
    const float* v_sa         = (const float*)d_in[8];
    const float* o_sa         = (const float*)d_in[9];
    const float* ln_sa_s      = (const float*)d_in[10];
    const float* ln_sa_b      = (const float*)d_in[11];
    const float* ln_pre_ca_b  = (const float*)d_in[12];
    const float* q_ca         = (const float*)d_in[13];
    const float* k_ca         = (const float*)d_in[14];
    const float* v_ca         = (const float*)d_in[15];
    const float* o_ca         = (const float*)d_in[16];
    const float* ln_ca_s      = (const float*)d_in[17];
    const float* ln_ca_b      = (const float*)d_in[18];
    const float* glu_ln0_b    = (const float*)d_in[19];
    const float* fc0_w        = (const float*)d_in[20];
    const float* fc1_w        = (const float*)d_in[21];
    const float* glu_ln1_s    = (const float*)d_in[22];
    const float* glu_ln1_b    = (const float*)d_in[23];
    const float* fc2_w        = (const float*)d_in[24];

    float* out_dec  = (float*)d_out;
    float* out_attn = out_dec + (size_t)BB * EE;

    float *x0, *q, *attn, *ds1, *ds2, *x1, *q1, *ekv, *z2, *part;
    __half *enc_h, *wk_h, *wv_h;
    cudaGetSymbolAddress((void**)&x0,   g_x0);
    cudaGetSymbolAddress((void**)&q,    g_q);
    cudaGetSymbolAddress((void**)&attn, g_attn);
    cudaGetSymbolAddress((void**)&ds1,  g_ds1);
    cudaGetSymbolAddress((void**)&ds2,  g_ds2);
    cudaGetSymbolAddress((void**)&x1,   g_x1);
    cudaGetSymbolAddress((void**)&q1,   g_q1);
    cudaGetSymbolAddress((void**)&ekv,  g_ekv);
    cudaGetSymbolAddress((void**)&z2,   g_z2);
    cudaGetSymbolAddress((void**)&part, g_part);
    cudaGetSymbolAddress((void**)&enc_h, g_enc_h);
    cudaGetSymbolAddress((void**)&wk_h,  g_wk_h);
    cudaGetSymbolAddress((void**)&wv_h,  g_wv_h);

    cudaFuncSetAttribute(GEMM_SMALL_T, cudaFuncAttributeMaxDynamicSharedMemorySize, SMEM_SMALL);
    cudaFuncSetAttribute(gemm_h16,     cudaFuncAttributeMaxDynamicSharedMemorySize, SMEM_H16);

    float* ek = ekv;
    float* ev = ekv + (size_t)BB * TT * EE;

    // ---- persistent handles (created once; see round-7 note) ---------------
    static cudaStream_t sA = nullptr, sB = nullptr;
    static cudaEvent_t eFork = nullptr, eCopy = nullptr, eGemm = nullptr;
    if (sA == nullptr) {
        cudaStreamCreateWithFlags(&sA, cudaStreamNonBlocking);
        cudaStreamCreateWithFlags(&sB, cudaStreamNonBlocking);
        cudaEventCreateWithFlags(&eFork, cudaEventDisableTiming);
        cudaEventCreateWithFlags(&eCopy, cudaEventDisableTiming);
        cudaEventCreateWithFlags(&eGemm, cudaEventDisableTiming);
    }

    cudaEventRecord(eFork, 0);
    cudaStreamWaitEvent(sA, eFork, 0);
    cudaStreamWaitEvent(sB, eFork, 0);

    // branch A: KV-cache pass-through copy (CE)
    cudaMemcpyAsync(out_attn, attn_in, (size_t)2 * BB * II * EE * sizeof(float),
                    cudaMemcpyDeviceToDevice, sA);
    cudaEventRecord(eCopy, sA);

    // branch B: f32->f16 conversion + big ek/ev GEMM (round-7 config)
    {
        const int na = BB * TT * EE, nb = EE * EE, nc = EE * EE;
        const int tot = na + nb + nc;
        f2h3_kernel<<<(tot / 8 + 255) / 256, 256, 0, sB>>>(enc, enc_h, na,
                                                           k_ca, wk_h, nb,
                                                           v_ca, wv_h, nc);
        gemm_h16<<<dim3(EE / 128, (BB * TT) / 128, 2), 256, SMEM_H16, sB>>>(
            enc_h, wk_h, wv_h, ekv, BB * TT, EE, EE);
        cudaEventRecord(eGemm, sB);
    }

    // ---- main chain: self-attention block ----------------------------------
    ln_kernel<<<BB, 256>>>(ds_in, nullptr, ln_pre_sa_b, nullptr, x0, EE);
    GEMM_SMALL_T<<<dim3(EE/64, 1, 3*4), 256, SMEM_SMALL>>>(x0, k_sa, v_sa, q_sa,
                                                           part, BB, EE, EE, 4);
    cudaStreamWaitEvent(0, eCopy, 0);
    reduce_qkv_scatter<<<(3*BB*EE/4 + 255)/256, 256>>>(part, q, out_attn, token_index, 4);
    self_attn_kernel<<<BB*HH, 256>>>(q, out_attn, token_index, attn);
    GEMM_SMALL_T<<<dim3(EE/64, 1, 8), 256, SMEM_SMALL>>>(attn, o_sa, o_sa, o_sa,
                                                         part, BB, EE, EE, 8);
    ln_reduce_kernel<8><<<BB, 256>>>(part, ln_sa_s, ln_sa_b, ds_in, ds1);

    // ---- cross-attention block ----------------------------------------------
    ln_kernel<<<BB, 256>>>(ds1, nullptr, ln_pre_ca_b, nullptr, x1, EE);
    GEMM_SMALL_T<<<dim3(EE/64, 1, 8), 256, SMEM_SMALL>>>(x1, q_ca, q_ca, q_ca,
                                                         part, BB, EE, EE, 8);
    reduce_ws<<<(BB*EE/4 + 255)/256, 256>>>(part, q1, BB*EE, 1, 8);
    cudaStreamWaitEvent(0, eGemm, 0);
    cross_attn_kernel<<<BB*HH, 256>>>(q1, ek, ev, attn_mask, attn);
    GEMM_SMALL_T<<<dim3(EE/64, 1, 8), 256, SMEM_SMALL>>>(attn, o_ca, o_ca, o_ca,
                                                         part, BB, EE, EE, 8);
    ln_reduce_kernel<8><<<BB, 256>>>(part, ln_ca_s, ln_ca_b, ds1, ds2);

    // ---- GLU feed-forward block ---------------------------------------------
    ln_kernel<<<BB, 256>>>(ds2, nullptr, glu_ln0_b, nullptr, x0, EE);
    GEMM_SMALL_T<<<dim3(GG/64, 1, 2*4), 256, SMEM_SMALL>>>(x0, fc0_w, fc1_w, fc1_w,
                                                           part, BB, GG, EE, 4);
    ln_glu_kernel<4><<<BB, 256>>>(part, glu_ln1_s, glu_ln1_b, z2);
    GEMM_SMALL_T<<<dim3(EE/64, 1, 8), 256, SMEM_SMALL>>>(z2, fc2_w, fc2_w, fc2_w,
                                                         part, BB, EE, GG, 8);
    reduce_add<8><<<(BB*EE/4 + 255)/256, 256>>>(part, ds2, out_dec, BB*EE);
}